// round 1
// baseline (speedup 1.0000x reference)
#include <cuda_runtime.h>
#include <math.h>

#define TB_E      64
#define NTHREADS  128
#define WN        2560
#define NCHUNKS   40

// ---------------- CG table storage (filled by setup kernel) ----------------
// layout: [0]=C000(1), [1..9]=C011, [10..18]=C101, [19..27]=C110,
//         [28..54]=C111, [55..99]=C112, [100..144]=C121
__device__ float g_CG[160];

__constant__ int   c_MID_OFF[7] = {0,16,64,112,128,176,256};
__constant__ int   c_MID_DJ[6]  = {1,3,3,1,3,5};
__constant__ int   c_TP1_I1[6]  = {0,0,1,1,1,1};
__constant__ int   c_TP1_I2[6]  = {0,1,0,1,1,1};
__constant__ int   c_TP1_CG[6]  = {0,1,10,19,28,55};
__constant__ float c_TP1_PW[6]  = {1.f,1.7320508075688772f,1.7320508075688772f,1.f,
                                   1.7320508075688772f,2.2360679774997896f};

#define S1 0.08838834764831845f /* sqrt(3/384) */
__constant__ int   c_P_I1[10] = {0,0,0,0,1,1,1,1,1,1};
__constant__ int   c_P_I2[10] = {0,1,2,3,0,1,2,3,4,5};
__constant__ int   c_P_IO[10] = {0,1,1,0,1,0,0,1,1,1};
__constant__ int   c_P_CG[10] = {0,1,1,0,10,19,19,10,28,100};
__constant__ float c_P_PW[10] = {0.0625f,S1,S1,0.0625f,S1,0.0625f,0.0625f,S1,S1,S1};

// ---------------- setup kernel: compute real CG tensors (reference transliteration) ----
struct Cx { double re, im; };
__device__ __forceinline__ Cx cxmul(Cx a, Cx b){ Cx r; r.re=a.re*b.re-a.im*b.im; r.im=a.re*b.im+a.im*b.re; return r; }
__device__ double dfact(int n){ double r=1.0; for(int i=2;i<=n;i++) r*=(double)i; return r; }

__device__ void qmat(int l, Cx* Q){
    int d=2*l+1;
    for(int i=0;i<d*d;i++){ Q[i].re=0; Q[i].im=0; }
    double s2 = 1.0/sqrt(2.0);
    for(int m=-l;m<0;m++){
        Q[(l+m)*d + (l-m)].re = s2;
        Q[(l+m)*d + (l+m)].im = -s2;
    }
    Q[l*d+l].re = 1.0;
    for(int m=1;m<=l;m++){
        double sg = (m&1)? -1.0 : 1.0;
        Q[(l+m)*d + (l+m)].re = sg*s2;
        Q[(l+m)*d + (l-m)].im = sg*s2;
    }
    Cx f;
    int lm = l & 3;
    if (lm==0){f.re=1;f.im=0;} else if(lm==1){f.re=0;f.im=-1;}
    else if(lm==2){f.re=-1;f.im=0;} else {f.re=0;f.im=1;}
    for(int i=0;i<d*d;i++) Q[i]=cxmul(Q[i],f);
}

__device__ void real_cg_dev(int l1,int l2,int l3, float* out){
    int d1=2*l1+1, d2=2*l2+1, d3=2*l3+1;
    double C[45];
    for(int i=0;i<d1*d2*d3;i++) C[i]=0.0;
    for(int m1=-l1;m1<=l1;m1++) for(int m2=-l2;m2<=l2;m2++){
        int m3=m1+m2; if (m3<-l3 || m3>l3) continue;
        double pref = sqrt((2*l3+1)*dfact(l1+l2-l3)*dfact(l1-l2+l3)*dfact(-l1+l2+l3)/dfact(l1+l2+l3+1));
        pref *= sqrt(dfact(l1+m1)*dfact(l1-m1)*dfact(l2+m2)*dfact(l2-m2)*dfact(l3+m3)*dfact(l3-m3));
        int kmin=0; if (l2-l3-m1>kmin) kmin=l2-l3-m1; if (l1-l3+m2>kmin) kmin=l1-l3+m2;
        int kmax=l1+l2-l3; if (l1-m1<kmax) kmax=l1-m1; if (l2+m2<kmax) kmax=l2+m2;
        double s=0.0;
        for(int k=kmin;k<=kmax;k++){
            double den = dfact(k)*dfact(l1+l2-l3-k)*dfact(l1-m1-k)*dfact(l2+m2-k)
                       * dfact(l3-l2+m1+k)*dfact(l3-l1-m2+k);
            s += ((k&1)? -1.0 : 1.0)/den;
        }
        C[((l1+m1)*d2 + (l2+m2))*d3 + (l3+m3)] = pref*s;
    }
    Cx Q1[25],Q2[25],Q3[25];
    qmat(l1,Q1); qmat(l2,Q2); qmat(l3,Q3);
    double R[45]; double nrm=0.0;
    for(int j=0;j<d1;j++) for(int lI=0;lI<d2;lI++) for(int m=0;m<d3;m++){
        Cx acc; acc.re=0; acc.im=0;
        for(int i=0;i<d1;i++) for(int k=0;k<d2;k++){
            Cx q12 = cxmul(Q1[i*d1+j], Q2[k*d2+lI]);
            for(int n=0;n<d3;n++){
                double c = C[(i*d2+k)*d3+n];
                if (c==0.0) continue;
                Cx q3c = Q3[n*d3+m]; q3c.im = -q3c.im;
                Cx t = cxmul(q12, q3c);
                acc.re += t.re*c; acc.im += t.im*c;
            }
        }
        R[(j*d2+lI)*d3+m] = acc.re;
        nrm += acc.re*acc.re;
    }
    double inv = 1.0/sqrt(nrm);
    for(int i=0;i<d1*d2*d3;i++) out[i] = (float)(R[i]*inv);
}

__global__ void setup_cg_kernel(){
    if (threadIdx.x==0 && blockIdx.x==0){
        real_cg_dev(0,0,0, g_CG+0);
        real_cg_dev(0,1,1, g_CG+1);
        real_cg_dev(1,0,1, g_CG+10);
        real_cg_dev(1,1,0, g_CG+19);
        real_cg_dev(1,1,1, g_CG+28);
        real_cg_dev(1,1,2, g_CG+55);
        real_cg_dev(1,2,1, g_CG+100);
    }
}

__global__ void zero_kernel(float* out, int n){
    int i = blockIdx.x*blockDim.x + threadIdx.x;
    if (i < n) out[i] = 0.f;
}

// ---------------- main fused conv kernel ----------------
extern "C" __global__ void __launch_bounds__(NTHREADS)
conv_kernel(const float* __restrict__ node_pos,
            const float* __restrict__ edge_type,
            const float* __restrict__ W0g,
            const float* __restrict__ W1g,
            const int*   __restrict__ esrc,
            const int*   __restrict__ edst,
            float* __restrict__ out,
            float silu_c)
{
    extern __shared__ float sm[];
    float* sH   = sm;                 // [64 h][64 e]   4096
    float* sW1  = sH  + 64*64;        // [64 h][64 c]   4096  (prologue alias: sET)
    float* sMID = sW1 + 64*64;        // [64 e][256]   16384  (prologue alias: sW0 in first 1024)
    float* sXS  = sMID + 64*256;      // [64 e][16]     1024
    float* sXD  = sXS + 64*16;        //                1024
    float* sOUT = sXD + 64*16;        //                1024
    float* sCG  = sOUT + 64*16;       //                 160
    int*   sSrc = (int*)(sCG + 160);  //                  64
    int*   sDst = sSrc + 64;          //                  64

    float* sET = sW1;    // [64 e][16] used only before main loop
    float* sW0 = sMID;   // [16 i][64 h] used only before mid computation

    const int tid = threadIdx.x;
    const int e0  = blockIdx.x * TB_E;

    for (int i=tid;i<160;i+=NTHREADS) sCG[i]=g_CG[i];
    if (tid < 64){ sSrc[tid]=esrc[e0+tid]; sDst[tid]=edst[e0+tid]; }
    for (int i=tid;i<TB_E*16;i+=NTHREADS) sOUT[i]=0.f;
    __syncthreads();

    // gather node features + edge types (float4), load W0 (scaled by 1/sqrt(16))
    for (int i=tid;i<TB_E*4;i+=NTHREADS){
        int e=i>>2, q=i&3;
        ((float4*)(sXS+e*16))[q] = ((const float4*)(node_pos + (size_t)sSrc[e]*16))[q];
        ((float4*)(sXD+e*16))[q] = ((const float4*)(node_pos + (size_t)sDst[e]*16))[q];
        ((float4*)(sET+e*16))[q] = ((const float4*)(edge_type + (size_t)(e0+e)*16))[q];
    }
    for (int i=tid;i<16*64;i+=NTHREADS) sW0[i] = W0g[i]*0.25f;
    __syncthreads();

    // hidden: H[h][e] = silu_c * silu( et[e] . W0[:,h] )
    for (int i=tid;i<TB_E*64;i+=NTHREADS){
        int e=i&63, h=i>>6;
        const float* et = sET + e*16;
        float acc=0.f;
        #pragma unroll
        for (int k=0;k<16;k++) acc += et[k]*sW0[k*64+h];
        sH[h*64+e] = silu_c * acc / (1.f + expf(-acc));
    }
    __syncthreads();   // H done reading sW0 before sMID clobbers it

    // tp1: mid (uvuv FullTensorProduct), [e][256]
    for (int i=tid;i<TB_E*256;i+=NTHREADS){
        int e=i>>8, m=i&255;
        int io=0;
        while (m >= c_MID_OFF[io+1]) io++;
        int rel = m - c_MID_OFF[io];
        int dj  = c_MID_DJ[io];
        int v   = rel/dj, j = rel - v*dj;
        int a = v>>2, b = v&3;
        int i1 = c_TP1_I1[io], i2 = c_TP1_I2[io];
        int di1 = i1?3:1, dj1 = i2?3:1;
        const float* cg = sCG + c_TP1_CG[io];
        const float* xs = sXS + e*16;
        const float* xd = sXD + e*16;
        float acc=0.f;
        for (int ii=0; ii<di1; ii++){
            float xv = i1 ? xs[4+a*3+ii] : xs[a];
            for (int jj=0; jj<dj1; jj++){
                float dv = i2 ? xd[4+b*3+jj] : xd[b];
                acc += xv*dv*cg[(ii*dj1+jj)*dj + j];
            }
        }
        sMID[e*256+m] = c_TP1_PW[io]*acc;
    }

    const int te = tid>>3;   // 0..15 -> edges te*4..te*4+3
    const int tc = tid&7;    // 0..7  -> cols  tc*8..tc*8+7 within chunk
    float outL[4][16];
    #pragma unroll
    for (int a=0;a<4;a++){
        #pragma unroll
        for (int b=0;b<16;b++) outL[a][b]=0.f;
    }

    for (int chunk=0; chunk<NCHUNKS; chunk++){
        __syncthreads();
        // load W1 chunk (cols chunk*64..+63), scaled by 1/sqrt(64)
        for (int i=tid;i<1024;i+=NTHREADS){
            int h=i>>4, c4=i&15;
            float4 w = *((const float4*)(W1g + (size_t)h*WN + chunk*64 + c4*4));
            w.x*=0.125f; w.y*=0.125f; w.z*=0.125f; w.w*=0.125f;
            *((float4*)(sW1 + h*64 + c4*4)) = w;
        }
        __syncthreads();

        // register-tiled GEMM: y[4 edges][8 cols]
        float y[4][8];
        #pragma unroll
        for (int a=0;a<4;a++){
            #pragma unroll
            for (int c=0;c<8;c++) y[a][c]=0.f;
        }
        #pragma unroll 4
        for (int h=0;h<64;h++){
            float4 A  = *((float4*)(sH  + h*64 + te*4));
            float4 B0 = *((float4*)(sW1 + h*64 + tc*8));
            float4 B1 = *((float4*)(sW1 + h*64 + tc*8 + 4));
            float av[4] = {A.x,A.y,A.z,A.w};
            float bv[8] = {B0.x,B0.y,B0.z,B0.w,B1.x,B1.y,B1.z,B1.w};
            #pragma unroll
            for (int a=0;a<4;a++){
                #pragma unroll
                for (int c=0;c<8;c++) y[a][c] += av[a]*bv[c];
            }
        }

        // consume y: n = chunk*64 + tc*8 + c ; n = p*256 + u*64 + v*4 + w
        #pragma unroll
        for (int g=0; g<2; g++){
            int nb = chunk*64 + tc*8 + g*4;
            int p  = nb>>8;
            int r  = nb&255;
            int u  = r>>6;
            int v  = (r>>2)&15;
            int i1 = c_P_I1[p], i2 = c_P_I2[p], io = c_P_IO[p];
            int dj = c_MID_DJ[i2];
            int di = i1?3:1;
            const float* cg = sCG + c_P_CG[p];
            float pw = c_P_PW[p];
            int midb = c_MID_OFF[i2] + v*dj;
            #pragma unroll
            for (int eL=0; eL<4; eL++){
                int e = te*4+eL;
                const float* xs = sXS + e*16;
                const float* md = sMID + e*256 + midb;
                float z0=0.f,z1=0.f,z2=0.f;
                for (int ii=0; ii<di; ii++){
                    float xv = i1 ? xs[4+u*3+ii] : xs[u];
                    for (int jj=0; jj<dj; jj++){
                        float t = xv*md[jj];
                        if (io){
                            const float* c = cg + (ii*dj+jj)*3;
                            z0 += t*c[0]; z1 += t*c[1]; z2 += t*c[2];
                        } else {
                            z0 += t*cg[ii*dj+jj];
                        }
                    }
                }
                if (io==0){
                    #pragma unroll
                    for (int w=0;w<4;w++) outL[eL][w] += pw*y[eL][g*4+w]*z0;
                } else {
                    #pragma unroll
                    for (int w=0;w<4;w++){
                        float yy = pw*y[eL][g*4+w];
                        outL[eL][4+3*w+0] += yy*z0;
                        outL[eL][4+3*w+1] += yy*z1;
                        outL[eL][4+3*w+2] += yy*z2;
                    }
                }
            }
        }
    }

    __syncthreads();
    #pragma unroll
    for (int eL=0; eL<4; eL++){
        int e = te*4+eL;
        #pragma unroll
        for (int d=0; d<16; d++) atomicAdd(&sOUT[e*16+d], outL[eL][d]);
    }
    __syncthreads();
    const float scale = 0.3535533905932738f; // 1/sqrt(NUM_NEIGHBORS=8)
    for (int i=tid;i<TB_E*16;i+=NTHREADS){
        int e=i>>4, d=i&15;
        atomicAdd(out + (size_t)sDst[e]*16 + d, sOUT[e*16+d]*scale);
    }
}

// ---------------- launch ----------------
extern "C" void kernel_launch(void* const* d_in, const int* in_sizes, int n_in,
                              void* d_out, int out_size)
{
    const float* node_pos  = (const float*)d_in[0];
    const float* edge_type = (const float*)d_in[1];
    const float* W0        = (const float*)d_in[2];
    const float* W1        = (const float*)d_in[3];
    const int*   esrc      = (const int*)d_in[4];
    const int*   edst      = (const int*)d_in[5];
    float*       out       = (float*)d_out;

    // SILU_C exactly as the reference computes it (200001-pt grid on [-12,12])
    double dx = 24.0/200000.0, s = 0.0;
    for (int i=0;i<=200000;i++){
        double x   = -12.0 + dx*(double)i;
        double phi = exp(-0.5*x*x)*0.3989422804014327; // 1/sqrt(2*pi)
        double sl  = x/(1.0+exp(-x));
        s += sl*sl*phi;
    }
    float silu_c = (float)(1.0/sqrt(s*dx));

    const int E = in_sizes[4];            // 65536
    const int nblocks = E / TB_E;         // 1024

    size_t smem = (size_t)(64*64 + 64*64 + 64*256 + 64*16*3 + 160)*sizeof(float) + 128*sizeof(int);
    cudaFuncSetAttribute(conv_kernel, cudaFuncAttributeMaxDynamicSharedMemorySize, (int)smem);

    setup_cg_kernel<<<1,32>>>();
    zero_kernel<<<(out_size+255)/256,256>>>(out, out_size);
    conv_kernel<<<nblocks, NTHREADS, smem>>>(node_pos, edge_type, W0, W1, esrc, edst, out, silu_c);
}

// round 2
// speedup vs baseline: 1.7043x; 1.7043x over previous
#include <cuda_runtime.h>
#include <math.h>

#define TB_E      64
#define NTHREADS  128
#define WN        2560
#define NCHUNKS   40

// ---------------- compile-time path tables ----------------
// mid irreps (from full TP, uvuv): offsets/dims in the 256-float per-edge mid vector
constexpr int   H_MID_OFF[6] = {0,16,64,112,128,176};
constexpr int   H_MID_DJ[6]  = {1,3,3,1,3,5};
// tp1 instructions
constexpr int   H_T1_I1[6] = {0,0,1,1,1,1};
constexpr int   H_T1_I2[6] = {0,1,0,1,1,1};
constexpr int   H_T1_CG[6] = {0,1,10,19,28,55};
constexpr float H_T1_PW[6] = {1.f,1.7320508075688772f,1.7320508075688772f,1.f,
                              1.7320508075688772f,2.2360679774997896f};
// tp2 paths
#define S1c 0.08838834764831845f /* sqrt(3/384) */
constexpr int   HP_I1[10] = {0,0,0,0,1,1,1,1,1,1};
constexpr int   HP_I2[10] = {0,1,2,3,0,1,2,3,4,5};
constexpr int   HP_IO[10] = {0,1,1,0,1,0,0,1,1,1};
constexpr int   HP_CG[10] = {0,1,1,0,10,19,19,10,28,100};
constexpr float HP_PW[10] = {0.0625f,S1c,S1c,0.0625f,S1c,0.0625f,0.0625f,S1c,S1c,S1c};

// CG table layout: [0]=C000(1), [1..9]=C011, [10..18]=C101, [19..27]=C110,
//                  [28..54]=C111, [55..99]=C112, [100..144]=C121
struct ConvConsts {
    float cg[160];
    float silu_c;
};

// ---------------- host-side CG computation (reference transliteration) ----------------
struct CxH { double re, im; };
static CxH cxmulH(CxH a, CxH b){ CxH r; r.re=a.re*b.re-a.im*b.im; r.im=a.re*b.im+a.im*b.re; return r; }
static double dfactH(int n){ double r=1.0; for(int i=2;i<=n;i++) r*=(double)i; return r; }

static void qmatH(int l, CxH* Q){
    int d=2*l+1;
    for(int i=0;i<d*d;i++){ Q[i].re=0; Q[i].im=0; }
    double s2 = 1.0/sqrt(2.0);
    for(int m=-l;m<0;m++){
        Q[(l+m)*d + (l-m)].re = s2;
        Q[(l+m)*d + (l+m)].im = -s2;
    }
    Q[l*d+l].re = 1.0;
    for(int m=1;m<=l;m++){
        double sg = (m&1)? -1.0 : 1.0;
        Q[(l+m)*d + (l+m)].re = sg*s2;
        Q[(l+m)*d + (l-m)].im = sg*s2;
    }
    CxH f;
    int lm = l & 3;
    if (lm==0){f.re=1;f.im=0;} else if(lm==1){f.re=0;f.im=-1;}
    else if(lm==2){f.re=-1;f.im=0;} else {f.re=0;f.im=1;}
    for(int i=0;i<d*d;i++) Q[i]=cxmulH(Q[i],f);
}

static void real_cg_host(int l1,int l2,int l3, float* out){
    int d1=2*l1+1, d2=2*l2+1, d3=2*l3+1;
    double C[45];
    for(int i=0;i<d1*d2*d3;i++) C[i]=0.0;
    for(int m1=-l1;m1<=l1;m1++) for(int m2=-l2;m2<=l2;m2++){
        int m3=m1+m2; if (m3<-l3 || m3>l3) continue;
        double pref = sqrt((2*l3+1)*dfactH(l1+l2-l3)*dfactH(l1-l2+l3)*dfactH(-l1+l2+l3)/dfactH(l1+l2+l3+1));
        pref *= sqrt(dfactH(l1+m1)*dfactH(l1-m1)*dfactH(l2+m2)*dfactH(l2-m2)*dfactH(l3+m3)*dfactH(l3-m3));
        int kmin=0; if (l2-l3-m1>kmin) kmin=l2-l3-m1; if (l1-l3+m2>kmin) kmin=l1-l3+m2;
        int kmax=l1+l2-l3; if (l1-m1<kmax) kmax=l1-m1; if (l2+m2<kmax) kmax=l2+m2;
        double s=0.0;
        for(int k=kmin;k<=kmax;k++){
            double den = dfactH(k)*dfactH(l1+l2-l3-k)*dfactH(l1-m1-k)*dfactH(l2+m2-k)
                       * dfactH(l3-l2+m1+k)*dfactH(l3-l1-m2+k);
            s += ((k&1)? -1.0 : 1.0)/den;
        }
        C[((l1+m1)*d2 + (l2+m2))*d3 + (l3+m3)] = pref*s;
    }
    CxH Q1[25],Q2[25],Q3[25];
    qmatH(l1,Q1); qmatH(l2,Q2); qmatH(l3,Q3);
    double R[45]; double nrm=0.0;
    for(int j=0;j<d1;j++) for(int lI=0;lI<d2;lI++) for(int m=0;m<d3;m++){
        CxH acc; acc.re=0; acc.im=0;
        for(int i=0;i<d1;i++) for(int k=0;k<d2;k++){
            CxH q12 = cxmulH(Q1[i*d1+j], Q2[k*d2+lI]);
            for(int n=0;n<d3;n++){
                double c = C[(i*d2+k)*d3+n];
                if (c==0.0) continue;
                CxH q3c = Q3[n*d3+m]; q3c.im = -q3c.im;
                CxH t = cxmulH(q12, q3c);
                acc.re += t.re*c; acc.im += t.im*c;
            }
        }
        R[(j*d2+lI)*d3+m] = acc.re;
        nrm += acc.re*acc.re;
    }
    double inv = 1.0/sqrt(nrm);
    for(int i=0;i<d1*d2*d3;i++) out[i] = (float)(R[i]*inv);
}

// ---------------- device: specialized tp1 (mid) ----------------
template<int MIo>
__device__ __forceinline__ void compute_mid(
    const float* __restrict__ sXS, const float* __restrict__ sXD,
    float* __restrict__ sMID, const float* __restrict__ sCG, int tid)
{
    constexpr int I1  = H_T1_I1[MIo];
    constexpr int I2  = H_T1_I2[MIo];
    constexpr int DJm = H_MID_DJ[MIo];
    constexpr int MOFF= H_MID_OFF[MIo];
    constexpr int CGO = H_T1_CG[MIo];
    constexpr int D1  = I1 ? 3 : 1;
    constexpr int D2  = I2 ? 3 : 1;
    constexpr float PW = H_T1_PW[MIo];
    for (int i=tid; i<TB_E*16*DJm; i+=NTHREADS){
        int e = i/(16*DJm);
        int r = i - e*(16*DJm);
        int v = r/DJm;
        int j = r - v*DJm;
        int a = v>>2, b = v&3;
        const float* xs = sXS + e*16;
        const float* xd = sXD + e*16;
        float acc = 0.f;
        #pragma unroll
        for (int ii=0; ii<D1; ii++){
            float xv = I1 ? xs[4+a*3+ii] : xs[a];
            #pragma unroll
            for (int jj=0; jj<D2; jj++){
                float dv = I2 ? xd[4+b*3+jj] : xd[b];
                acc += xv*dv*sCG[CGO + (ii*D2+jj)*DJm + j];
            }
        }
        sMID[e*256 + MOFF + v*DJm + j] = PW*acc;
    }
}

// ---------------- device: specialized tp2 epilogue ----------------
template<int P>
__device__ __forceinline__ void consume_path(
    int u, int tc, int te,
    const float* __restrict__ sXS,
    const float* __restrict__ sMID,
    const float* __restrict__ sCG,
    const float (&y)[4][8],
    float (&outL)[4][16])
{
    constexpr int I1  = HP_I1[P];
    constexpr int I2  = HP_I2[P];
    constexpr int IO  = HP_IO[P];
    constexpr int CGO = HP_CG[P];
    constexpr int DJ  = H_MID_DJ[I2];
    constexpr int MOFF= H_MID_OFF[I2];
    constexpr int DI  = I1 ? 3 : 1;
    constexpr float PW = HP_PW[P];

    #pragma unroll
    for (int g=0; g<2; g++){
        const int v = tc*2 + g;
        #pragma unroll
        for (int eL=0; eL<4; eL++){
            const int e = te*4 + eL;
            const float* xs = sXS + e*16;
            const float* md = sMID + e*256 + MOFF + v*DJ;
            float m[DJ];
            #pragma unroll
            for (int jj=0; jj<DJ; jj++) m[jj] = md[jj];
            float xv[DI];
            #pragma unroll
            for (int ii=0; ii<DI; ii++) xv[ii] = I1 ? xs[4+u*3+ii] : xs[u];

            float z0=0.f, z1=0.f, z2=0.f;
            #pragma unroll
            for (int ii=0; ii<DI; ii++){
                #pragma unroll
                for (int jj=0; jj<DJ; jj++){
                    float t = xv[ii]*m[jj];
                    if constexpr (IO==1){
                        z0 += t*sCG[CGO + (ii*DJ+jj)*3 + 0];
                        z1 += t*sCG[CGO + (ii*DJ+jj)*3 + 1];
                        z2 += t*sCG[CGO + (ii*DJ+jj)*3 + 2];
                    } else {
                        z0 += t*sCG[CGO + ii*DJ+jj];
                    }
                }
            }
            if constexpr (IO==0){
                #pragma unroll
                for (int w=0; w<4; w++)
                    outL[eL][w] += PW*y[eL][g*4+w]*z0;
            } else {
                #pragma unroll
                for (int w=0; w<4; w++){
                    float yy = PW*y[eL][g*4+w];
                    outL[eL][4+3*w+0] += yy*z0;
                    outL[eL][4+3*w+1] += yy*z1;
                    outL[eL][4+3*w+2] += yy*z2;
                }
            }
        }
    }
}

__global__ void zero_kernel(float* out, int n){
    int i = blockIdx.x*blockDim.x + threadIdx.x;
    if (i < n) out[i] = 0.f;
}

// ---------------- main fused conv kernel ----------------
extern "C" __global__ void __launch_bounds__(NTHREADS)
conv_kernel(const float* __restrict__ node_pos,
            const float* __restrict__ edge_type,
            const float* __restrict__ W0g,
            const float* __restrict__ W1g,
            const int*   __restrict__ esrc,
            const int*   __restrict__ edst,
            float* __restrict__ out,
            const __grid_constant__ ConvConsts cc)
{
    extern __shared__ float sm[];
    float* sH   = sm;                 // [64 h][64 e]   4096 floats
    float* sW1  = sH  + 64*64;        // [64 h][64 c]   4096
    float* sMID = sW1 + 64*64;        // [64 e][256]   16384  (prologue alias: sW0)
    float* sXS  = sMID + 64*256;      // [64 e][16]     1024
    float* sXD  = sXS + 64*16;        //                1024
    float* sOUT = sXD + 64*16;        //                1024
    float* sCG  = sOUT + 64*16;       //                 160
    float* sETT = sCG + 160;          // [16 k][64 e]   1024 (transposed edge types)
    int*   sSrc = (int*)(sETT + 1024);
    int*   sDst = sSrc + 64;

    float* sW0 = sMID;   // [16 i][64 h] alias, used only before mid computation

    const int tid = threadIdx.x;
    const int e0  = blockIdx.x * TB_E;

    for (int i=tid;i<160;i+=NTHREADS) sCG[i]=cc.cg[i];
    if (tid < 64){ sSrc[tid]=esrc[e0+tid]; sDst[tid]=edst[e0+tid]; }
    for (int i=tid;i<TB_E*16;i+=NTHREADS) sOUT[i]=0.f;
    __syncthreads();

    // gather node features (float4) + edge types (transposed store)
    for (int i=tid;i<TB_E*4;i+=NTHREADS){
        int e=i>>2, q=i&3;
        ((float4*)(sXS+e*16))[q] = ((const float4*)(node_pos + (size_t)sSrc[e]*16))[q];
        ((float4*)(sXD+e*16))[q] = ((const float4*)(node_pos + (size_t)sDst[e]*16))[q];
        float4 t = ((const float4*)(edge_type + (size_t)(e0+e)*16))[q];
        sETT[(4*q+0)*64 + e] = t.x;
        sETT[(4*q+1)*64 + e] = t.y;
        sETT[(4*q+2)*64 + e] = t.z;
        sETT[(4*q+3)*64 + e] = t.w;
    }
    for (int i=tid;i<16*64;i+=NTHREADS) sW0[i] = W0g[i]*0.25f;
    __syncthreads();

    // hidden: H[h][e] = silu_c * silu( et[e] . W0[:,h] )   (conflict-free: e across lanes)
    for (int i=tid;i<TB_E*64;i+=NTHREADS){
        int e=i&63, h=i>>6;
        float acc=0.f;
        #pragma unroll
        for (int k=0;k<16;k++) acc += sETT[k*64+e]*sW0[k*64+h];
        sH[h*64+e] = cc.silu_c * acc / (1.f + expf(-acc));
    }
    __syncthreads();   // done reading sW0 before sMID clobbers it

    // tp1: mid (specialized per mid-irrep)
    compute_mid<0>(sXS, sXD, sMID, sCG, tid);
    compute_mid<1>(sXS, sXD, sMID, sCG, tid);
    compute_mid<2>(sXS, sXD, sMID, sCG, tid);
    compute_mid<3>(sXS, sXD, sMID, sCG, tid);
    compute_mid<4>(sXS, sXD, sMID, sCG, tid);
    compute_mid<5>(sXS, sXD, sMID, sCG, tid);

    const int te = tid>>3;   // 0..15 -> edges te*4..te*4+3
    const int tc = tid&7;    // 0..7  -> cols  tc*8..tc*8+7 within chunk
    float outL[4][16];
    #pragma unroll
    for (int a=0;a<4;a++){
        #pragma unroll
        for (int b=0;b<16;b++) outL[a][b]=0.f;
    }

    for (int chunk=0; chunk<NCHUNKS; chunk++){
        __syncthreads();
        // load W1 chunk (cols chunk*64..+63), scaled by 1/sqrt(64)
        for (int i=tid;i<1024;i+=NTHREADS){
            int h=i>>4, c4=i&15;
            float4 w = *((const float4*)(W1g + (size_t)h*WN + chunk*64 + c4*4));
            w.x*=0.125f; w.y*=0.125f; w.z*=0.125f; w.w*=0.125f;
            *((float4*)(sW1 + h*64 + c4*4)) = w;
        }
        __syncthreads();

        // register-tiled GEMM: y[4 edges][8 cols]
        float y[4][8];
        #pragma unroll
        for (int a=0;a<4;a++){
            #pragma unroll
            for (int c=0;c<8;c++) y[a][c]=0.f;
        }
        #pragma unroll 8
        for (int h=0;h<64;h++){
            float4 A  = *((float4*)(sH  + h*64 + te*4));
            float4 B0 = *((float4*)(sW1 + h*64 + tc*8));
            float4 B1 = *((float4*)(sW1 + h*64 + tc*8 + 4));
            float av[4] = {A.x,A.y,A.z,A.w};
            float bv[8] = {B0.x,B0.y,B0.z,B0.w,B1.x,B1.y,B1.z,B1.w};
            #pragma unroll
            for (int a=0;a<4;a++){
                #pragma unroll
                for (int c=0;c<8;c++) y[a][c] += av[a]*bv[c];
            }
        }

        // specialized consumption: p = chunk>>2 and u = chunk&3 are uniform per chunk
        const int u = chunk & 3;
        switch (chunk >> 2){
            case 0: consume_path<0>(u, tc, te, sXS, sMID, sCG, y, outL); break;
            case 1: consume_path<1>(u, tc, te, sXS, sMID, sCG, y, outL); break;
            case 2: consume_path<2>(u, tc, te, sXS, sMID, sCG, y, outL); break;
            case 3: consume_path<3>(u, tc, te, sXS, sMID, sCG, y, outL); break;
            case 4: consume_path<4>(u, tc, te, sXS, sMID, sCG, y, outL); break;
            case 5: consume_path<5>(u, tc, te, sXS, sMID, sCG, y, outL); break;
            case 6: consume_path<6>(u, tc, te, sXS, sMID, sCG, y, outL); break;
            case 7: consume_path<7>(u, tc, te, sXS, sMID, sCG, y, outL); break;
            case 8: consume_path<8>(u, tc, te, sXS, sMID, sCG, y, outL); break;
            case 9: consume_path<9>(u, tc, te, sXS, sMID, sCG, y, outL); break;
        }
    }

    __syncthreads();
    #pragma unroll
    for (int eL=0; eL<4; eL++){
        int e = te*4+eL;
        #pragma unroll
        for (int d=0; d<16; d++) atomicAdd(&sOUT[e*16+d], outL[eL][d]);
    }
    __syncthreads();
    const float scale = 0.3535533905932738f; // 1/sqrt(NUM_NEIGHBORS=8)
    for (int i=tid;i<TB_E*16;i+=NTHREADS){
        int e=i>>4, d=i&15;
        atomicAdd(out + (size_t)sDst[e]*16 + d, sOUT[e*16+d]*scale);
    }
}

// ---------------- launch ----------------
extern "C" void kernel_launch(void* const* d_in, const int* in_sizes, int n_in,
                              void* d_out, int out_size)
{
    const float* node_pos  = (const float*)d_in[0];
    const float* edge_type = (const float*)d_in[1];
    const float* W0        = (const float*)d_in[2];
    const float* W1        = (const float*)d_in[3];
    const int*   esrc      = (const int*)d_in[4];
    const int*   edst      = (const int*)d_in[5];
    float*       out       = (float*)d_out;

    ConvConsts cc;
    for (int i=0;i<160;i++) cc.cg[i]=0.f;
    real_cg_host(0,0,0, cc.cg+0);
    real_cg_host(0,1,1, cc.cg+1);
    real_cg_host(1,0,1, cc.cg+10);
    real_cg_host(1,1,0, cc.cg+19);
    real_cg_host(1,1,1, cc.cg+28);
    real_cg_host(1,1,2, cc.cg+55);
    real_cg_host(1,2,1, cc.cg+100);

    // SILU_C exactly as the reference computes it (200001-pt grid on [-12,12])
    double dx = 24.0/200000.0, s = 0.0;
    for (int i=0;i<=200000;i++){
        double x   = -12.0 + dx*(double)i;
        double phi = exp(-0.5*x*x)*0.3989422804014327;
        double sl  = x/(1.0+exp(-x));
        s += sl*sl*phi;
    }
    cc.silu_c = (float)(1.0/sqrt(s*dx));

    const int E = in_sizes[4];            // 65536
    const int nblocks = E / TB_E;         // 1024

    size_t smem = (size_t)(64*64 + 64*64 + 64*256 + 64*16*3 + 160 + 1024)*sizeof(float)
                + 128*sizeof(int);
    cudaFuncSetAttribute(conv_kernel, cudaFuncAttributeMaxDynamicSharedMemorySize, (int)smem);

    zero_kernel<<<(out_size+255)/256,256>>>(out, out_size);
    conv_kernel<<<nblocks, NTHREADS, smem>>>(node_pos, edge_type, W0, W1, esrc, edst, out, cc);
}

// round 3
// speedup vs baseline: 3.1148x; 1.8276x over previous
#include <cuda_runtime.h>
#include <math.h>

#define TB_E      64
#define NTHREADS  256
#define WN        2560
#define NCHUNKS   40

// ---------------- compile-time path tables ----------------
constexpr int   H_MID_OFF[6] = {0,16,64,112,128,176};
constexpr int   H_MID_DJ[6]  = {1,3,3,1,3,5};
constexpr int   H_T1_I1[6] = {0,0,1,1,1,1};
constexpr int   H_T1_I2[6] = {0,1,0,1,1,1};
constexpr int   H_T1_CG[6] = {0,1,10,19,28,55};
constexpr float H_T1_PW[6] = {1.f,1.7320508075688772f,1.7320508075688772f,1.f,
                              1.7320508075688772f,2.2360679774997896f};
#define S1c 0.08838834764831845f /* sqrt(3/384) */
constexpr int   HP_I1[10] = {0,0,0,0,1,1,1,1,1,1};
constexpr int   HP_I2[10] = {0,1,2,3,0,1,2,3,4,5};
constexpr int   HP_IO[10] = {0,1,1,0,1,0,0,1,1,1};
constexpr int   HP_CG[10] = {0,1,1,0,10,19,19,10,28,100};
constexpr float HP_PW[10] = {0.0625f,S1c,S1c,0.0625f,S1c,0.0625f,0.0625f,S1c,S1c,S1c};

// CG table layout: [0]=C000(1), [1..9]=C011, [10..18]=C101, [19..27]=C110,
//                  [28..54]=C111, [55..99]=C112, [100..144]=C121
struct ConvConsts {
    float cg[160];
    float silu_c;
};

// ---------------- host-side CG computation (reference transliteration) ----------------
struct CxH { double re, im; };
static CxH cxmulH(CxH a, CxH b){ CxH r; r.re=a.re*b.re-a.im*b.im; r.im=a.re*b.im+a.im*b.re; return r; }
static double dfactH(int n){ double r=1.0; for(int i=2;i<=n;i++) r*=(double)i; return r; }

static void qmatH(int l, CxH* Q){
    int d=2*l+1;
    for(int i=0;i<d*d;i++){ Q[i].re=0; Q[i].im=0; }
    double s2 = 1.0/sqrt(2.0);
    for(int m=-l;m<0;m++){
        Q[(l+m)*d + (l-m)].re = s2;
        Q[(l+m)*d + (l+m)].im = -s2;
    }
    Q[l*d+l].re = 1.0;
    for(int m=1;m<=l;m++){
        double sg = (m&1)? -1.0 : 1.0;
        Q[(l+m)*d + (l+m)].re = sg*s2;
        Q[(l+m)*d + (l-m)].im = sg*s2;
    }
    CxH f;
    int lm = l & 3;
    if (lm==0){f.re=1;f.im=0;} else if(lm==1){f.re=0;f.im=-1;}
    else if(lm==2){f.re=-1;f.im=0;} else {f.re=0;f.im=1;}
    for(int i=0;i<d*d;i++) Q[i]=cxmulH(Q[i],f);
}

static void real_cg_host(int l1,int l2,int l3, float* out){
    int d1=2*l1+1, d2=2*l2+1, d3=2*l3+1;
    double C[45];
    for(int i=0;i<d1*d2*d3;i++) C[i]=0.0;
    for(int m1=-l1;m1<=l1;m1++) for(int m2=-l2;m2<=l2;m2++){
        int m3=m1+m2; if (m3<-l3 || m3>l3) continue;
        double pref = sqrt((2*l3+1)*dfactH(l1+l2-l3)*dfactH(l1-l2+l3)*dfactH(-l1+l2+l3)/dfactH(l1+l2+l3+1));
        pref *= sqrt(dfactH(l1+m1)*dfactH(l1-m1)*dfactH(l2+m2)*dfactH(l2-m2)*dfactH(l3+m3)*dfactH(l3-m3));
        int kmin=0; if (l2-l3-m1>kmin) kmin=l2-l3-m1; if (l1-l3+m2>kmin) kmin=l1-l3+m2;
        int kmax=l1+l2-l3; if (l1-m1<kmax) kmax=l1-m1; if (l2+m2<kmax) kmax=l2+m2;
        double s=0.0;
        for(int k=kmin;k<=kmax;k++){
            double den = dfactH(k)*dfactH(l1+l2-l3-k)*dfactH(l1-m1-k)*dfactH(l2+m2-k)
                       * dfactH(l3-l2+m1+k)*dfactH(l3-l1-m2+k);
            s += ((k&1)? -1.0 : 1.0)/den;
        }
        C[((l1+m1)*d2 + (l2+m2))*d3 + (l3+m3)] = pref*s;
    }
    CxH Q1[25],Q2[25],Q3[25];
    qmatH(l1,Q1); qmatH(l2,Q2); qmatH(l3,Q3);
    double R[45]; double nrm=0.0;
    for(int j=0;j<d1;j++) for(int lI=0;lI<d2;lI++) for(int m=0;m<d3;m++){
        CxH acc; acc.re=0; acc.im=0;
        for(int i=0;i<d1;i++) for(int k=0;k<d2;k++){
            CxH q12 = cxmulH(Q1[i*d1+j], Q2[k*d2+lI]);
            for(int n=0;n<d3;n++){
                double c = C[(i*d2+k)*d3+n];
                if (c==0.0) continue;
                CxH q3c = Q3[n*d3+m]; q3c.im = -q3c.im;
                CxH t = cxmulH(q12, q3c);
                acc.re += t.re*c; acc.im += t.im*c;
            }
        }
        R[(j*d2+lI)*d3+m] = acc.re;
        nrm += acc.re*acc.re;
    }
    double inv = 1.0/sqrt(nrm);
    for(int i=0;i<d1*d2*d3;i++) out[i] = (float)(R[i]*inv);
}

// ---------------- device: specialized tp1 (mid) ----------------
template<int MIo>
__device__ __forceinline__ void compute_mid(
    const float* __restrict__ sXS, const float* __restrict__ sXD,
    float* __restrict__ sMID, const float* __restrict__ sCG, int tid)
{
    constexpr int I1  = H_T1_I1[MIo];
    constexpr int I2  = H_T1_I2[MIo];
    constexpr int DJm = H_MID_DJ[MIo];
    constexpr int MOFF= H_MID_OFF[MIo];
    constexpr int CGO = H_T1_CG[MIo];
    constexpr int D1  = I1 ? 3 : 1;
    constexpr int D2  = I2 ? 3 : 1;
    constexpr float PW = H_T1_PW[MIo];
    for (int i=tid; i<TB_E*16*DJm; i+=NTHREADS){
        int e = i/(16*DJm);
        int r = i - e*(16*DJm);
        int v = r/DJm;
        int j = r - v*DJm;
        int a = v>>2, b = v&3;
        const float* xs = sXS + e*16;
        const float* xd = sXD + e*16;
        float acc = 0.f;
        #pragma unroll
        for (int ii=0; ii<D1; ii++){
            float xv = I1 ? xs[4+a*3+ii] : xs[a];
            #pragma unroll
            for (int jj=0; jj<D2; jj++){
                float dv = I2 ? xd[4+b*3+jj] : xd[b];
                acc += xv*dv*sCG[CGO + (ii*D2+jj)*DJm + j];
            }
        }
        sMID[e*256 + MOFF + v*DJm + j] = PW*acc;
    }
}

// ---------------- device: specialized tp2 epilogue (v = tc, 4 w per thread) ----------------
template<int P>
__device__ __forceinline__ void consume_path(
    int u, int v, int te,
    const float* __restrict__ sXS,
    const float* __restrict__ sMID,
    const float* __restrict__ sCG,
    const float (&y)[4][4],
    float (&outL)[4][16])
{
    constexpr int I1  = HP_I1[P];
    constexpr int I2  = HP_I2[P];
    constexpr int IO  = HP_IO[P];
    constexpr int CGO = HP_CG[P];
    constexpr int DJ  = H_MID_DJ[I2];
    constexpr int MOFF= H_MID_OFF[I2];
    constexpr int DI  = I1 ? 3 : 1;
    constexpr float PW = HP_PW[P];

    #pragma unroll
    for (int eL=0; eL<4; eL++){
        const int e = te*4 + eL;
        const float* xs = sXS + e*16;
        const float* md = sMID + e*256 + MOFF + v*DJ;
        float m[DJ];
        #pragma unroll
        for (int jj=0; jj<DJ; jj++) m[jj] = md[jj];
        float xv[DI];
        #pragma unroll
        for (int ii=0; ii<DI; ii++) xv[ii] = I1 ? xs[4+u*3+ii] : xs[u];

        float z0=0.f, z1=0.f, z2=0.f;
        #pragma unroll
        for (int ii=0; ii<DI; ii++){
            #pragma unroll
            for (int jj=0; jj<DJ; jj++){
                float t = xv[ii]*m[jj];
                if constexpr (IO==1){
                    z0 += t*sCG[CGO + (ii*DJ+jj)*3 + 0];
                    z1 += t*sCG[CGO + (ii*DJ+jj)*3 + 1];
                    z2 += t*sCG[CGO + (ii*DJ+jj)*3 + 2];
                } else {
                    z0 += t*sCG[CGO + ii*DJ+jj];
                }
            }
        }
        if constexpr (IO==0){
            #pragma unroll
            for (int w=0; w<4; w++)
                outL[eL][w] += PW*y[eL][w]*z0;
        } else {
            #pragma unroll
            for (int w=0; w<4; w++){
                float yy = PW*y[eL][w];
                outL[eL][4+3*w+0] += yy*z0;
                outL[eL][4+3*w+1] += yy*z1;
                outL[eL][4+3*w+2] += yy*z2;
            }
        }
    }
}

__global__ void zero_kernel(float* out, int n){
    int i = blockIdx.x*blockDim.x + threadIdx.x;
    if (i < n) out[i] = 0.f;
}

// ---------------- main fused conv kernel ----------------
extern "C" __global__ void __launch_bounds__(NTHREADS, 2)
conv_kernel(const float* __restrict__ node_pos,
            const float* __restrict__ edge_type,
            const float* __restrict__ W0g,
            const float* __restrict__ W1g,
            const int*   __restrict__ esrc,
            const int*   __restrict__ edst,
            float* __restrict__ out,
            const __grid_constant__ ConvConsts cc)
{
    extern __shared__ float sm[];
    float* sH   = sm;                 // [64 h][64 e]   4096 floats
    float* sW1  = sH  + 64*64;        // [64 h][64 c]   4096
    float* sMID = sW1 + 64*64;        // [64 e][256]   16384 (aliases: sW0, sETT; scratch later)
    float* sXS  = sMID + 64*256;      // [64 e][16]     1024
    float* sXD  = sXS + 64*16;        //                1024
    float* sCG  = sXD + 64*16;        //                 160
    int*   sSrc = (int*)(sCG + 160);  //                  64
    int*   sDst = sSrc + 64;          //                  64

    float* sETT = sMID;               // [16 k][64 e] alias, dead after hidden stage
    float* sW0  = sMID + 1024;        // [16 i][64 h] alias, dead after hidden stage

    const int tid = threadIdx.x;
    const int e0  = blockIdx.x * TB_E;

    for (int i=tid;i<160;i+=NTHREADS) sCG[i]=cc.cg[i];
    if (tid < 64){ sSrc[tid]=esrc[e0+tid]; sDst[tid]=edst[e0+tid]; }
    __syncthreads();

    // gather node features (float4) + edge types (transposed store)
    for (int i=tid;i<TB_E*4;i+=NTHREADS){
        int e=i>>2, q=i&3;
        ((float4*)(sXS+e*16))[q] = ((const float4*)(node_pos + (size_t)sSrc[e]*16))[q];
        ((float4*)(sXD+e*16))[q] = ((const float4*)(node_pos + (size_t)sDst[e]*16))[q];
        float4 t = ((const float4*)(edge_type + (size_t)(e0+e)*16))[q];
        sETT[(4*q+0)*64 + e] = t.x;
        sETT[(4*q+1)*64 + e] = t.y;
        sETT[(4*q+2)*64 + e] = t.z;
        sETT[(4*q+3)*64 + e] = t.w;
    }
    for (int i=tid;i<16*64;i+=NTHREADS) sW0[i] = W0g[i]*0.25f;
    __syncthreads();

    // hidden: H[h][e] = silu_c * silu( et[e] . W0[:,h] )
    for (int i=tid;i<TB_E*64;i+=NTHREADS){
        int e=i&63, h=i>>6;
        float acc=0.f;
        #pragma unroll
        for (int k=0;k<16;k++) acc += sETT[k*64+e]*sW0[k*64+h];
        sH[h*64+e] = cc.silu_c * acc / (1.f + expf(-acc));
    }
    __syncthreads();   // done reading sETT/sW0 before sMID clobbers them

    // tp1: mid (specialized per mid-irrep)
    compute_mid<0>(sXS, sXD, sMID, sCG, tid);
    compute_mid<1>(sXS, sXD, sMID, sCG, tid);
    compute_mid<2>(sXS, sXD, sMID, sCG, tid);
    compute_mid<3>(sXS, sXD, sMID, sCG, tid);
    compute_mid<4>(sXS, sXD, sMID, sCG, tid);
    compute_mid<5>(sXS, sXD, sMID, sCG, tid);

    const int te = tid>>4;   // 0..15 -> edges te*4..te*4+3
    const int tc = tid&15;   // 0..15 -> v = tc, cols v*4..v*4+3 within chunk
    float outL[4][16];
    #pragma unroll
    for (int a=0;a<4;a++){
        #pragma unroll
        for (int b=0;b<16;b++) outL[a][b]=0.f;
    }

    for (int chunk=0; chunk<NCHUNKS; chunk++){
        __syncthreads();
        // load W1 chunk (cols chunk*64..+63), scaled by 1/sqrt(64)
        for (int i=tid;i<1024;i+=NTHREADS){
            int h=i>>4, c4=i&15;
            float4 w = *((const float4*)(W1g + (size_t)h*WN + chunk*64 + c4*4));
            w.x*=0.125f; w.y*=0.125f; w.z*=0.125f; w.w*=0.125f;
            *((float4*)(sW1 + h*64 + c4*4)) = w;
        }
        __syncthreads();

        // register-tiled GEMM with packed f32x2 FMA: y[4 edges][4 cols]
        unsigned long long yp[2][4];   // [edge-pair][col], each = (e_even, e_odd)
        #pragma unroll
        for (int a=0;a<2;a++){
            #pragma unroll
            for (int c=0;c<4;c++) yp[a][c]=0ull;
        }
        #pragma unroll 8
        for (int h=0;h<64;h++){
            float4 A = *((float4*)(sH  + h*64 + te*4));
            float4 B = *((float4*)(sW1 + h*64 + tc*4));
            unsigned long long a01,a23,bb0,bb1,bb2,bb3;
            asm("mov.b64 %0,{%1,%2};" : "=l"(a01) : "f"(A.x), "f"(A.y));
            asm("mov.b64 %0,{%1,%2};" : "=l"(a23) : "f"(A.z), "f"(A.w));
            asm("mov.b64 %0,{%1,%1};" : "=l"(bb0) : "f"(B.x));
            asm("mov.b64 %0,{%1,%1};" : "=l"(bb1) : "f"(B.y));
            asm("mov.b64 %0,{%1,%1};" : "=l"(bb2) : "f"(B.z));
            asm("mov.b64 %0,{%1,%1};" : "=l"(bb3) : "f"(B.w));
            asm("fma.rn.f32x2 %0, %1, %2, %0;" : "+l"(yp[0][0]) : "l"(a01), "l"(bb0));
            asm("fma.rn.f32x2 %0, %1, %2, %0;" : "+l"(yp[0][1]) : "l"(a01), "l"(bb1));
            asm("fma.rn.f32x2 %0, %1, %2, %0;" : "+l"(yp[0][2]) : "l"(a01), "l"(bb2));
            asm("fma.rn.f32x2 %0, %1, %2, %0;" : "+l"(yp[0][3]) : "l"(a01), "l"(bb3));
            asm("fma.rn.f32x2 %0, %1, %2, %0;" : "+l"(yp[1][0]) : "l"(a23), "l"(bb0));
            asm("fma.rn.f32x2 %0, %1, %2, %0;" : "+l"(yp[1][1]) : "l"(a23), "l"(bb1));
            asm("fma.rn.f32x2 %0, %1, %2, %0;" : "+l"(yp[1][2]) : "l"(a23), "l"(bb2));
            asm("fma.rn.f32x2 %0, %1, %2, %0;" : "+l"(yp[1][3]) : "l"(a23), "l"(bb3));
        }
        float y[4][4];
        #pragma unroll
        for (int a=0;a<2;a++){
            #pragma unroll
            for (int c=0;c<4;c++)
                asm("mov.b64 {%0,%1},%2;" : "=f"(y[2*a][c]), "=f"(y[2*a+1][c]) : "l"(yp[a][c]));
        }

        // specialized consumption: p = chunk>>2 and u = chunk&3 are uniform per chunk
        const int u = chunk & 3;
        switch (chunk >> 2){
            case 0: consume_path<0>(u, tc, te, sXS, sMID, sCG, y, outL); break;
            case 1: consume_path<1>(u, tc, te, sXS, sMID, sCG, y, outL); break;
            case 2: consume_path<2>(u, tc, te, sXS, sMID, sCG, y, outL); break;
            case 3: consume_path<3>(u, tc, te, sXS, sMID, sCG, y, outL); break;
            case 4: consume_path<4>(u, tc, te, sXS, sMID, sCG, y, outL); break;
            case 5: consume_path<5>(u, tc, te, sXS, sMID, sCG, y, outL); break;
            case 6: consume_path<6>(u, tc, te, sXS, sMID, sCG, y, outL); break;
            case 7: consume_path<7>(u, tc, te, sXS, sMID, sCG, y, outL); break;
            case 8: consume_path<8>(u, tc, te, sXS, sMID, sCG, y, outL); break;
            case 9: consume_path<9>(u, tc, te, sXS, sMID, sCG, y, outL); break;
        }
    }

    // ---- cross-tc reduction via bank-staggered scratch (reuses dead sMID/sXS) ----
    __syncthreads();  // all consumers done reading sMID/sXS
    float* sSCR = sMID;               // 16 rows, stride 1028 floats (bank-staggered)
    #pragma unroll
    for (int eL=0; eL<4; eL++){
        int base = tc*1028 + (te*4+eL)*16;
        #pragma unroll
        for (int q=0; q<4; q++){
            *((float4*)(sSCR + base + q*4)) =
                make_float4(outL[eL][q*4+0], outL[eL][q*4+1], outL[eL][q*4+2], outL[eL][q*4+3]);
        }
    }
    __syncthreads();
    {
        // each thread reduces one float4 of the 64x16 output: idx = tid (256 float4s)
        int e  = tid >> 2;
        int dq = tid & 3;
        float4 acc = make_float4(0.f,0.f,0.f,0.f);
        #pragma unroll
        for (int t=0; t<16; t++){
            float4 v = *((float4*)(sSCR + t*1028 + e*16 + dq*4));
            acc.x += v.x; acc.y += v.y; acc.z += v.z; acc.w += v.w;
        }
        const float scale = 0.3535533905932738f; // 1/sqrt(NUM_NEIGHBORS=8)
        float* dst = out + (size_t)sDst[e]*16 + dq*4;
        atomicAdd(dst+0, acc.x*scale);
        atomicAdd(dst+1, acc.y*scale);
        atomicAdd(dst+2, acc.z*scale);
        atomicAdd(dst+3, acc.w*scale);
    }
}

// ---------------- launch ----------------
extern "C" void kernel_launch(void* const* d_in, const int* in_sizes, int n_in,
                              void* d_out, int out_size)
{
    const float* node_pos  = (const float*)d_in[0];
    const float* edge_type = (const float*)d_in[1];
    const float* W0        = (const float*)d_in[2];
    const float* W1        = (const float*)d_in[3];
    const int*   esrc      = (const int*)d_in[4];
    const int*   edst      = (const int*)d_in[5];
    float*       out       = (float*)d_out;

    ConvConsts cc;
    for (int i=0;i<160;i++) cc.cg[i]=0.f;
    real_cg_host(0,0,0, cc.cg+0);
    real_cg_host(0,1,1, cc.cg+1);
    real_cg_host(1,0,1, cc.cg+10);
    real_cg_host(1,1,0, cc.cg+19);
    real_cg_host(1,1,1, cc.cg+28);
    real_cg_host(1,1,2, cc.cg+55);
    real_cg_host(1,2,1, cc.cg+100);

    // SILU_C exactly as the reference computes it (200001-pt grid on [-12,12])
    double dx = 24.0/200000.0, s = 0.0;
    for (int i=0;i<=200000;i++){
        double x   = -12.0 + dx*(double)i;
        double phi = exp(-0.5*x*x)*0.3989422804014327;
        double sl  = x/(1.0+exp(-x));
        s += sl*sl*phi;
    }
    cc.silu_c = (float)(1.0/sqrt(s*dx));

    const int E = in_sizes[4];            // 65536
    const int nblocks = E / TB_E;         // 1024

    // floats: sH 4096 + sW1 4096 + sMID 16384 + sXS 1024 + sXD 1024 + sCG 160, + 128 ints
    size_t smem = (size_t)(4096 + 4096 + 16384 + 1024 + 1024 + 160)*sizeof(float)
                + 128*sizeof(int);
    cudaFuncSetAttribute(conv_kernel, cudaFuncAttributeMaxDynamicSharedMemorySize, (int)smem);

    zero_kernel<<<(out_size+255)/256,256>>>(out, out_size);
    conv_kernel<<<nblocks, NTHREADS, smem>>>(node_pos, edge_type, W0, W1, esrc, edst, out, cc);
}

// round 4
// speedup vs baseline: 3.3285x; 1.0686x over previous
#include <cuda_runtime.h>
#include <math.h>

#define TB_E      64
#define NTHREADS  256
#define WN        2560
#define NCHUNKS   20

typedef unsigned long long u64;

// ---------------- compile-time path tables ----------------
constexpr int   H_MID_OFF[6] = {0,16,64,112,128,176};
constexpr int   H_MID_DJ[6]  = {1,3,3,1,3,5};
constexpr int   H_T1_I1[6] = {0,0,1,1,1,1};
constexpr int   H_T1_I2[6] = {0,1,0,1,1,1};
constexpr int   H_T1_CG[6] = {0,1,10,19,28,55};
constexpr float H_T1_PW[6] = {1.f,1.7320508075688772f,1.7320508075688772f,1.f,
                              1.7320508075688772f,2.2360679774997896f};
#define S1c 0.08838834764831845f /* sqrt(3/384) */
constexpr int   HP_I1[10] = {0,0,0,0,1,1,1,1,1,1};
constexpr int   HP_I2[10] = {0,1,2,3,0,1,2,3,4,5};
constexpr int   HP_IO[10] = {0,1,1,0,1,0,0,1,1,1};
constexpr int   HP_CG[10] = {0,1,1,0,10,19,19,10,28,100};
constexpr float HP_PW[10] = {0.0625f,S1c,S1c,0.0625f,S1c,0.0625f,0.0625f,S1c,S1c,S1c};

// CG table layout: [0]=C000(1), [1..9]=C011, [10..18]=C101, [19..27]=C110,
//                  [28..54]=C111, [55..99]=C112, [100..144]=C121
struct ConvConsts {
    float cg[160];
    float silu_c;
};

// ---------------- f32x2 helpers ----------------
__device__ __forceinline__ u64 pk2(float lo, float hi){ u64 r; asm("mov.b64 %0,{%1,%2};" : "=l"(r) : "f"(lo), "f"(hi)); return r; }
__device__ __forceinline__ u64 dup2(float x){ u64 r; asm("mov.b64 %0,{%1,%1};" : "=l"(r) : "f"(x)); return r; }
__device__ __forceinline__ u64 mul2(u64 a, u64 b){ u64 r; asm("mul.rn.f32x2 %0,%1,%2;" : "=l"(r) : "l"(a), "l"(b)); return r; }
__device__ __forceinline__ void fma2(u64 &d, u64 a, u64 b){ asm("fma.rn.f32x2 %0,%1,%2,%0;" : "+l"(d) : "l"(a), "l"(b)); }
__device__ __forceinline__ u64 add2(u64 a, u64 b){ u64 r; asm("add.rn.f32x2 %0,%1,%2;" : "=l"(r) : "l"(a), "l"(b)); return r; }
__device__ __forceinline__ void upk2(u64 v, float &lo, float &hi){ asm("mov.b64 {%0,%1},%2;" : "=f"(lo), "=f"(hi) : "l"(v)); }

// ---------------- host-side CG computation (reference transliteration) ----------------
struct CxH { double re, im; };
static CxH cxmulH(CxH a, CxH b){ CxH r; r.re=a.re*b.re-a.im*b.im; r.im=a.re*b.im+a.im*b.re; return r; }
static double dfactH(int n){ double r=1.0; for(int i=2;i<=n;i++) r*=(double)i; return r; }

static void qmatH(int l, CxH* Q){
    int d=2*l+1;
    for(int i=0;i<d*d;i++){ Q[i].re=0; Q[i].im=0; }
    double s2 = 1.0/sqrt(2.0);
    for(int m=-l;m<0;m++){
        Q[(l+m)*d + (l-m)].re = s2;
        Q[(l+m)*d + (l+m)].im = -s2;
    }
    Q[l*d+l].re = 1.0;
    for(int m=1;m<=l;m++){
        double sg = (m&1)? -1.0 : 1.0;
        Q[(l+m)*d + (l+m)].re = sg*s2;
        Q[(l+m)*d + (l-m)].im = sg*s2;
    }
    CxH f;
    int lm = l & 3;
    if (lm==0){f.re=1;f.im=0;} else if(lm==1){f.re=0;f.im=-1;}
    else if(lm==2){f.re=-1;f.im=0;} else {f.re=0;f.im=1;}
    for(int i=0;i<d*d;i++) Q[i]=cxmulH(Q[i],f);
}

static void real_cg_host(int l1,int l2,int l3, float* out){
    int d1=2*l1+1, d2=2*l2+1, d3=2*l3+1;
    double C[45];
    for(int i=0;i<d1*d2*d3;i++) C[i]=0.0;
    for(int m1=-l1;m1<=l1;m1++) for(int m2=-l2;m2<=l2;m2++){
        int m3=m1+m2; if (m3<-l3 || m3>l3) continue;
        double pref = sqrt((2*l3+1)*dfactH(l1+l2-l3)*dfactH(l1-l2+l3)*dfactH(-l1+l2+l3)/dfactH(l1+l2+l3+1));
        pref *= sqrt(dfactH(l1+m1)*dfactH(l1-m1)*dfactH(l2+m2)*dfactH(l2-m2)*dfactH(l3+m3)*dfactH(l3-m3));
        int kmin=0; if (l2-l3-m1>kmin) kmin=l2-l3-m1; if (l1-l3+m2>kmin) kmin=l1-l3+m2;
        int kmax=l1+l2-l3; if (l1-m1<kmax) kmax=l1-m1; if (l2+m2<kmax) kmax=l2+m2;
        double s=0.0;
        for(int k=kmin;k<=kmax;k++){
            double den = dfactH(k)*dfactH(l1+l2-l3-k)*dfactH(l1-m1-k)*dfactH(l2+m2-k)
                       * dfactH(l3-l2+m1+k)*dfactH(l3-l1-m2+k);
            s += ((k&1)? -1.0 : 1.0)/den;
        }
        C[((l1+m1)*d2 + (l2+m2))*d3 + (l3+m3)] = pref*s;
    }
    CxH Q1[25],Q2[25],Q3[25];
    qmatH(l1,Q1); qmatH(l2,Q2); qmatH(l3,Q3);
    double R[45]; double nrm=0.0;
    for(int j=0;j<d1;j++) for(int lI=0;lI<d2;lI++) for(int m=0;m<d3;m++){
        CxH acc; acc.re=0; acc.im=0;
        for(int i=0;i<d1;i++) for(int k=0;k<d2;k++){
            CxH q12 = cxmulH(Q1[i*d1+j], Q2[k*d2+lI]);
            for(int n=0;n<d3;n++){
                double c = C[(i*d2+k)*d3+n];
                if (c==0.0) continue;
                CxH q3c = Q3[n*d3+m]; q3c.im = -q3c.im;
                CxH t = cxmulH(q12, q3c);
                acc.re += t.re*c; acc.im += t.im*c;
            }
        }
        R[(j*d2+lI)*d3+m] = acc.re;
        nrm += acc.re*acc.re;
    }
    double inv = 1.0/sqrt(nrm);
    for(int i=0;i<d1*d2*d3;i++) out[i] = (float)(R[i]*inv);
}

// ---------------- specialized tp2 epilogue, mid recomputed on the fly ----------------
// thread covers edges te*4..te*4+3 (2 f32x2 pairs) and cols tc*8..tc*8+7 (g=0,1; w=0..3)
template<int P>
__device__ __forceinline__ void consume_path(
    int u, int tc, int te,
    const float* __restrict__ sXSt,
    const float* __restrict__ sXDt,
    const float* __restrict__ sCG,
    const u64 (&yp)[2][8],
    u64 (&outP)[2][16])
{
    constexpr int I1  = HP_I1[P];
    constexpr int I2  = HP_I2[P];
    constexpr int IO  = HP_IO[P];
    constexpr int CGO2= HP_CG[P];
    constexpr int DJ  = H_MID_DJ[I2];
    constexpr int DI  = I1 ? 3 : 1;
    // tp1 spec for mid irrep I2 (recompute mid from xs,xd)
    constexpr int J1  = H_T1_I1[I2];
    constexpr int J2  = H_T1_I2[I2];
    constexpr int D1  = J1 ? 3 : 1;
    constexpr int D2  = J2 ? 3 : 1;
    constexpr int CGO1= H_T1_CG[I2];
    constexpr float PWT = H_T1_PW[I2]*HP_PW[P];  // fold tp1 pw into final scale

    #pragma unroll
    for (int g=0; g<2; g++){
        const int v = ((tc&7)<<1) | g;
        const int a = v>>2, b = v&3;
        #pragma unroll
        for (int q=0; q<2; q++){
            const int eP = te*4 + q*2;
            // mid recompute (unscaled): m[jj] = sum_{ii,kk} xs[a,ii]*xd[b,kk]*CG1
            u64 xsA[D1], xdB[D2];
            #pragma unroll
            for (int ii=0; ii<D1; ii++)
                xsA[ii] = *(const u64*)(sXSt + (J1 ? (4+a*3+ii) : a)*64 + eP);
            #pragma unroll
            for (int kk=0; kk<D2; kk++)
                xdB[kk] = *(const u64*)(sXDt + (J2 ? (4+b*3+kk) : b)*64 + eP);
            u64 m[DJ];
            #pragma unroll
            for (int jj=0; jj<DJ; jj++) m[jj]=0ull;
            #pragma unroll
            for (int ii=0; ii<D1; ii++){
                #pragma unroll
                for (int kk=0; kk<D2; kk++){
                    u64 pr = mul2(xsA[ii], xdB[kk]);
                    #pragma unroll
                    for (int jj=0; jj<DJ; jj++)
                        fma2(m[jj], pr, dup2(sCG[CGO1 + (ii*D2+kk)*DJ + jj]));
                }
            }
            // z_k = sum_{ii,jj} xs[u,ii]*m[jj]*CG2
            u64 z0=0ull, z1=0ull, z2=0ull;
            #pragma unroll
            for (int ii=0; ii<DI; ii++){
                u64 xu = *(const u64*)(sXSt + (I1 ? (4+u*3+ii) : u)*64 + eP);
                #pragma unroll
                for (int jj=0; jj<DJ; jj++){
                    u64 t = mul2(xu, m[jj]);
                    if constexpr (IO==1){
                        fma2(z0, t, dup2(sCG[CGO2 + (ii*DJ+jj)*3 + 0]));
                        fma2(z1, t, dup2(sCG[CGO2 + (ii*DJ+jj)*3 + 1]));
                        fma2(z2, t, dup2(sCG[CGO2 + (ii*DJ+jj)*3 + 2]));
                    } else {
                        fma2(z0, t, dup2(sCG[CGO2 + ii*DJ+jj]));
                    }
                }
            }
            const u64 pw2 = dup2(PWT);
            z0 = mul2(z0, pw2);
            if constexpr (IO==1){ z1 = mul2(z1, pw2); z2 = mul2(z2, pw2); }
            #pragma unroll
            for (int w=0; w<4; w++){
                u64 y = yp[q][g*4+w];
                if constexpr (IO==0){
                    fma2(outP[q][w], y, z0);
                } else {
                    fma2(outP[q][4+3*w+0], y, z0);
                    fma2(outP[q][4+3*w+1], y, z1);
                    fma2(outP[q][4+3*w+2], y, z2);
                }
            }
        }
    }
}

__global__ void zero_kernel(float* out, int n){
    int i = blockIdx.x*blockDim.x + threadIdx.x;
    if (i < n) out[i] = 0.f;
}

// ---------------- main fused conv kernel ----------------
extern "C" __global__ void __launch_bounds__(NTHREADS, 2)
conv_kernel(const float* __restrict__ node_pos,
            const float* __restrict__ edge_type,
            const float* __restrict__ W0g,
            const float* __restrict__ W1g,
            const int*   __restrict__ esrc,
            const int*   __restrict__ edst,
            float* __restrict__ out,
            const __grid_constant__ ConvConsts cc)
{
    extern __shared__ float sm[];
    float* sH   = sm;                 // [64 h][64 e]        4096 floats
    float* sW1  = sH  + 64*64;        // [64 h][128 c perm]  8192
    float* sXSt = sW1 + 64*128;       // [16 d][64 e]        1024 (transposed)
    float* sXDt = sXSt + 1024;        //                     1024
    float* sCG  = sXDt + 1024;        //                      160
    int*   sSrc = (int*)(sCG + 160);  //                       64
    int*   sDst = sSrc + 64;          //                       64

    float* sETT = sW1;                // [16 k][64 e] alias, dead after hidden stage
    float* sW0  = sW1 + 1024;         // [16 i][64 h] alias, dead after hidden stage

    const int tid = threadIdx.x;
    const int e0  = blockIdx.x * TB_E;

    for (int i=tid;i<160;i+=NTHREADS) sCG[i]=cc.cg[i];
    if (tid < 64){ sSrc[tid]=esrc[e0+tid]; sDst[tid]=edst[e0+tid]; }
    __syncthreads();

    // gather node features transposed + edge types transposed
    {
        int e=tid>>2, q=tid&3;
        float4 xs = ((const float4*)(node_pos + (size_t)sSrc[e]*16))[q];
        float4 xd = ((const float4*)(node_pos + (size_t)sDst[e]*16))[q];
        float4 t  = ((const float4*)(edge_type + (size_t)(e0+e)*16))[q];
        sXSt[(4*q+0)*64 + e] = xs.x;  sXSt[(4*q+1)*64 + e] = xs.y;
        sXSt[(4*q+2)*64 + e] = xs.z;  sXSt[(4*q+3)*64 + e] = xs.w;
        sXDt[(4*q+0)*64 + e] = xd.x;  sXDt[(4*q+1)*64 + e] = xd.y;
        sXDt[(4*q+2)*64 + e] = xd.z;  sXDt[(4*q+3)*64 + e] = xd.w;
        sETT[(4*q+0)*64 + e] = t.x;   sETT[(4*q+1)*64 + e] = t.y;
        sETT[(4*q+2)*64 + e] = t.z;   sETT[(4*q+3)*64 + e] = t.w;
    }
    for (int i=tid;i<16*64;i+=NTHREADS) sW0[i] = W0g[i]*0.25f;
    __syncthreads();

    // hidden: H[h][e] = silu_c * silu( et[e] . W0[:,h] )
    for (int i=tid;i<TB_E*64;i+=NTHREADS){
        int e=i&63, h=i>>6;
        float acc=0.f;
        #pragma unroll
        for (int k=0;k<16;k++) acc += sETT[k*64+e]*sW0[k*64+h];
        sH[h*64+e] = cc.silu_c * acc / (1.f + expf(-acc));
    }

    const int te = tid>>4;   // 0..15 -> edges te*4..te*4+3
    const int tc = tid&15;   // 0..15 -> cols tc*8..tc*8+7 within 128-wide chunk
    u64 outP[2][16];
    #pragma unroll
    for (int q=0;q<2;q++){
        #pragma unroll
        for (int k=0;k<16;k++) outP[q][k]=0ull;
    }

    for (int chunk=0; chunk<NCHUNKS; chunk++){
        __syncthreads();
        // load W1 chunk (128 cols), scaled 1/8, stored PERMUTED: c=tc*8+g*4+w -> g*64+tc*4+w
        for (int i=tid;i<2048;i+=NTHREADS){
            int h=i>>5, c4=i&31;                   // c4 = c/4
            float4 w = *((const float4*)(W1g + (size_t)h*WN + chunk*128 + c4*4));
            w.x*=0.125f; w.y*=0.125f; w.z*=0.125f; w.w*=0.125f;
            int off = ((c4&1)<<6) + ((c4>>1)<<2);  // g*64 + tc*4
            *((float4*)(sW1 + h*128 + off)) = w;
        }
        __syncthreads();

        // register-tiled GEMM (f32x2): y[2 edge-pairs][8 cols]
        u64 yp[2][8];
        #pragma unroll
        for (int q=0;q<2;q++){
            #pragma unroll
            for (int c=0;c<8;c++) yp[q][c]=0ull;
        }
        #pragma unroll 8
        for (int h=0;h<64;h++){
            float4 A  = *((float4*)(sH  + h*64  + te*4));
            float4 B0 = *((float4*)(sW1 + h*128 + tc*4));        // g=0 cols
            float4 B1 = *((float4*)(sW1 + h*128 + 64 + tc*4));   // g=1 cols
            u64 a01 = pk2(A.x,A.y), a23 = pk2(A.z,A.w);
            u64 b[8] = {dup2(B0.x),dup2(B0.y),dup2(B0.z),dup2(B0.w),
                        dup2(B1.x),dup2(B1.y),dup2(B1.z),dup2(B1.w)};
            #pragma unroll
            for (int c=0;c<8;c++){
                fma2(yp[0][c], a01, b[c]);
                fma2(yp[1][c], a23, b[c]);
            }
        }

        // p = chunk>>1 uniform; u = (chunk&1)*2 + (tc>>3)
        const int u = ((chunk&1)<<1) | (tc>>3);
        switch (chunk >> 1){
            case 0: consume_path<0>(u, tc, te, sXSt, sXDt, sCG, yp, outP); break;
            case 1: consume_path<1>(u, tc, te, sXSt, sXDt, sCG, yp, outP); break;
            case 2: consume_path<2>(u, tc, te, sXSt, sXDt, sCG, yp, outP); break;
            case 3: consume_path<3>(u, tc, te, sXSt, sXDt, sCG, yp, outP); break;
            case 4: consume_path<4>(u, tc, te, sXSt, sXDt, sCG, yp, outP); break;
            case 5: consume_path<5>(u, tc, te, sXSt, sXDt, sCG, yp, outP); break;
            case 6: consume_path<6>(u, tc, te, sXSt, sXDt, sCG, yp, outP); break;
            case 7: consume_path<7>(u, tc, te, sXSt, sXDt, sCG, yp, outP); break;
            case 8: consume_path<8>(u, tc, te, sXSt, sXDt, sCG, yp, outP); break;
            case 9: consume_path<9>(u, tc, te, sXSt, sXDt, sCG, yp, outP); break;
        }
    }

    // ---- reduce across the 16 tc lanes (xor shuffles stay within half-warp) ----
    #pragma unroll
    for (int msk=1; msk<16; msk<<=1){
        #pragma unroll
        for (int q=0;q<2;q++){
            #pragma unroll
            for (int k=0;k<16;k++){
                u64 o = __shfl_xor_sync(0xffffffffu, outP[q][k], msk);
                outP[q][k] = add2(outP[q][k], o);
            }
        }
    }
    __syncthreads();   // all reads of sH/sW1 complete before reuse as sOUT
    float* sOUT = sm;  // [64 e][16]
    if (tc == 0){
        #pragma unroll
        for (int q=0;q<2;q++){
            int e = te*4 + q*2;
            #pragma unroll
            for (int k=0;k<16;k++){
                float lo,hi; upk2(outP[q][k], lo, hi);
                sOUT[e*16 + k]      = lo;
                sOUT[(e+1)*16 + k]  = hi;
            }
        }
    }
    __syncthreads();
    {
        int e  = tid >> 2;
        int dq = tid & 3;
        float4 v = *((float4*)(sOUT + e*16 + dq*4));
        const float scale = 0.3535533905932738f; // 1/sqrt(NUM_NEIGHBORS=8)
        float* dst = out + (size_t)sDst[e]*16 + dq*4;
        atomicAdd(dst+0, v.x*scale);
        atomicAdd(dst+1, v.y*scale);
        atomicAdd(dst+2, v.z*scale);
        atomicAdd(dst+3, v.w*scale);
    }
}

// ---------------- launch ----------------
extern "C" void kernel_launch(void* const* d_in, const int* in_sizes, int n_in,
                              void* d_out, int out_size)
{
    const float* node_pos  = (const float*)d_in[0];
    const float* edge_type = (const float*)d_in[1];
    const float* W0        = (const float*)d_in[2];
    const float* W1        = (const float*)d_in[3];
    const int*   esrc      = (const int*)d_in[4];
    const int*   edst      = (const int*)d_in[5];
    float*       out       = (float*)d_out;

    ConvConsts cc;
    for (int i=0;i<160;i++) cc.cg[i]=0.f;
    real_cg_host(0,0,0, cc.cg+0);
    real_cg_host(0,1,1, cc.cg+1);
    real_cg_host(1,0,1, cc.cg+10);
    real_cg_host(1,1,0, cc.cg+19);
    real_cg_host(1,1,1, cc.cg+28);
    real_cg_host(1,1,2, cc.cg+55);
    real_cg_host(1,2,1, cc.cg+100);

    // SILU_C exactly as the reference computes it (200001-pt grid on [-12,12])
    double dx = 24.0/200000.0, s = 0.0;
    for (int i=0;i<=200000;i++){
        double x   = -12.0 + dx*(double)i;
        double phi = exp(-0.5*x*x)*0.3989422804014327;
        double sl  = x/(1.0+exp(-x));
        s += sl*sl*phi;
    }
    cc.silu_c = (float)(1.0/sqrt(s*dx));

    const int E = in_sizes[4];            // 65536
    const int nblocks = E / TB_E;         // 1024

    // floats: sH 4096 + sW1 8192 + sXSt 1024 + sXDt 1024 + sCG 160, + 128 ints
    size_t smem = (size_t)(4096 + 8192 + 1024 + 1024 + 160)*sizeof(float)
                + 128*sizeof(int);
    cudaFuncSetAttribute(conv_kernel, cudaFuncAttributeMaxDynamicSharedMemorySize, (int)smem);

    zero_kernel<<<(out_size+255)/256,256>>>(out, out_size);
    conv_kernel<<<nblocks, NTHREADS, smem>>>(node_pos, edge_type, W0, W1, esrc, edst, out, cc);
}

// round 5
// speedup vs baseline: 3.4699x; 1.0425x over previous
#include <cuda_runtime.h>
#include <math.h>
#include <stdint.h>

#define TB_E      64
#define NTHREADS  256
#define WN        2560
#define NCHUNKS   20

typedef unsigned long long u64;

// ---------------- compile-time path tables ----------------
constexpr int   H_MID_DJ[6]  = {1,3,3,1,3,5};
constexpr int   H_T1_I1[6] = {0,0,1,1,1,1};
constexpr int   H_T1_I2[6] = {0,1,0,1,1,1};
constexpr int   H_T1_CG[6] = {0,1,10,19,28,55};
constexpr float H_T1_PW[6] = {1.f,1.7320508075688772f,1.7320508075688772f,1.f,
                              1.7320508075688772f,2.2360679774997896f};
#define S1c 0.08838834764831845f /* sqrt(3/384) */
constexpr int   HP_I1[10] = {0,0,0,0,1,1,1,1,1,1};
constexpr int   HP_I2[10] = {0,1,2,3,0,1,2,3,4,5};
constexpr int   HP_IO[10] = {0,1,1,0,1,0,0,1,1,1};
constexpr int   HP_CG[10] = {0,1,1,0,10,19,19,10,28,100};
constexpr float HP_PW[10] = {0.0625f,S1c,S1c,0.0625f,S1c,0.0625f,0.0625f,S1c,S1c,S1c};

// CG table layout: [0]=C000(1), [1..9]=C011, [10..18]=C101, [19..27]=C110,
//                  [28..54]=C111, [55..99]=C112, [100..144]=C121
struct ConvConsts {
    float cg[160];
    float silu_c;
};

// ---------------- f32x2 / tf32 / mma helpers ----------------
__device__ __forceinline__ u64 pk2(float lo, float hi){ u64 r; asm("mov.b64 %0,{%1,%2};" : "=l"(r) : "f"(lo), "f"(hi)); return r; }
__device__ __forceinline__ u64 dup2(float x){ u64 r; asm("mov.b64 %0,{%1,%1};" : "=l"(r) : "f"(x)); return r; }
__device__ __forceinline__ u64 mul2(u64 a, u64 b){ u64 r; asm("mul.rn.f32x2 %0,%1,%2;" : "=l"(r) : "l"(a), "l"(b)); return r; }
__device__ __forceinline__ void fma2(u64 &d, u64 a, u64 b){ asm("fma.rn.f32x2 %0,%1,%2,%0;" : "+l"(d) : "l"(a), "l"(b)); }
__device__ __forceinline__ u64 add2(u64 a, u64 b){ u64 r; asm("add.rn.f32x2 %0,%1,%2;" : "=l"(r) : "l"(a), "l"(b)); return r; }
__device__ __forceinline__ void upk2(u64 v, float &lo, float &hi){ asm("mov.b64 {%0,%1},%2;" : "=f"(lo), "=f"(hi) : "l"(v)); }

__device__ __forceinline__ uint32_t f2tf(float x){
    uint32_t r; asm("cvt.rna.tf32.f32 %0,%1;" : "=r"(r) : "f"(x)); return r;
}
__device__ __forceinline__ void split_tf(float x, uint32_t &hi, uint32_t &lo){
    hi = f2tf(x);
    lo = f2tf(x - __uint_as_float(hi));
}
__device__ __forceinline__ void mma_tf32(float (&c)[4],
    uint32_t a0, uint32_t a1, uint32_t a2, uint32_t a3, uint32_t b0, uint32_t b1)
{
    asm("mma.sync.aligned.m16n8k8.row.col.f32.tf32.tf32.f32 "
        "{%0,%1,%2,%3},{%4,%5,%6,%7},{%8,%9},{%0,%1,%2,%3};"
        : "+f"(c[0]),"+f"(c[1]),"+f"(c[2]),"+f"(c[3])
        : "r"(a0),"r"(a1),"r"(a2),"r"(a3),"r"(b0),"r"(b1));
}

// ---------------- host-side CG computation (reference transliteration) ----------------
struct CxH { double re, im; };
static CxH cxmulH(CxH a, CxH b){ CxH r; r.re=a.re*b.re-a.im*b.im; r.im=a.re*b.im+a.im*b.re; return r; }
static double dfactH(int n){ double r=1.0; for(int i=2;i<=n;i++) r*=(double)i; return r; }

static void qmatH(int l, CxH* Q){
    int d=2*l+1;
    for(int i=0;i<d*d;i++){ Q[i].re=0; Q[i].im=0; }
    double s2 = 1.0/sqrt(2.0);
    for(int m=-l;m<0;m++){
        Q[(l+m)*d + (l-m)].re = s2;
        Q[(l+m)*d + (l+m)].im = -s2;
    }
    Q[l*d+l].re = 1.0;
    for(int m=1;m<=l;m++){
        double sg = (m&1)? -1.0 : 1.0;
        Q[(l+m)*d + (l+m)].re = sg*s2;
        Q[(l+m)*d + (l-m)].im = sg*s2;
    }
    CxH f;
    int lm = l & 3;
    if (lm==0){f.re=1;f.im=0;} else if(lm==1){f.re=0;f.im=-1;}
    else if(lm==2){f.re=-1;f.im=0;} else {f.re=0;f.im=1;}
    for(int i=0;i<d*d;i++) Q[i]=cxmulH(Q[i],f);
}

static void real_cg_host(int l1,int l2,int l3, float* out){
    int d1=2*l1+1, d2=2*l2+1, d3=2*l3+1;
    double C[45];
    for(int i=0;i<d1*d2*d3;i++) C[i]=0.0;
    for(int m1=-l1;m1<=l1;m1++) for(int m2=-l2;m2<=l2;m2++){
        int m3=m1+m2; if (m3<-l3 || m3>l3) continue;
        double pref = sqrt((2*l3+1)*dfactH(l1+l2-l3)*dfactH(l1-l2+l3)*dfactH(-l1+l2+l3)/dfactH(l1+l2+l3+1));
        pref *= sqrt(dfactH(l1+m1)*dfactH(l1-m1)*dfactH(l2+m2)*dfactH(l2-m2)*dfactH(l3+m3)*dfactH(l3-m3));
        int kmin=0; if (l2-l3-m1>kmin) kmin=l2-l3-m1; if (l1-l3+m2>kmin) kmin=l1-l3+m2;
        int kmax=l1+l2-l3; if (l1-m1<kmax) kmax=l1-m1; if (l2+m2<kmax) kmax=l2+m2;
        double s=0.0;
        for(int k=kmin;k<=kmax;k++){
            double den = dfactH(k)*dfactH(l1+l2-l3-k)*dfactH(l1-m1-k)*dfactH(l2+m2-k)
                       * dfactH(l3-l2+m1+k)*dfactH(l3-l1-m2+k);
            s += ((k&1)? -1.0 : 1.0)/den;
        }
        C[((l1+m1)*d2 + (l2+m2))*d3 + (l3+m3)] = pref*s;
    }
    CxH Q1[25],Q2[25],Q3[25];
    qmatH(l1,Q1); qmatH(l2,Q2); qmatH(l3,Q3);
    double R[45]; double nrm=0.0;
    for(int j=0;j<d1;j++) for(int lI=0;lI<d2;lI++) for(int m=0;m<d3;m++){
        CxH acc; acc.re=0; acc.im=0;
        for(int i=0;i<d1;i++) for(int k=0;k<d2;k++){
            CxH q12 = cxmulH(Q1[i*d1+j], Q2[k*d2+lI]);
            for(int n=0;n<d3;n++){
                double c = C[(i*d2+k)*d3+n];
                if (c==0.0) continue;
                CxH q3c = Q3[n*d3+m]; q3c.im = -q3c.im;
                CxH t = cxmulH(q12, q3c);
                acc.re += t.re*c; acc.im += t.im*c;
            }
        }
        R[(j*d2+lI)*d3+m] = acc.re;
        nrm += acc.re*acc.re;
    }
    double inv = 1.0/sqrt(nrm);
    for(int i=0;i<d1*d2*d3;i++) out[i] = (float)(R[i]*inv);
}

// ---------------- specialized tp2 epilogue, mid recomputed on the fly ----------------
// One call handles one (v, w0) group for the edge PAIR (r1, r1+8) packed as f32x2.
// y0 = outputs (w0) for (r1,r2); y1 = outputs (w0+1).
template<int P>
__device__ __forceinline__ void consume_one(
    int u, int v, int w0, int pj,
    const float* __restrict__ sXSp,
    const float* __restrict__ sXDp,
    const float* __restrict__ sCG,
    u64 y0, u64 y1,
    u64 (&outP)[16])
{
    constexpr int I1  = HP_I1[P];
    constexpr int I2  = HP_I2[P];
    constexpr int IO  = HP_IO[P];
    constexpr int CGO2= HP_CG[P];
    constexpr int DJ  = H_MID_DJ[I2];
    constexpr int DI  = I1 ? 3 : 1;
    constexpr int J1  = H_T1_I1[I2];
    constexpr int J2  = H_T1_I2[I2];
    constexpr int D1  = J1 ? 3 : 1;
    constexpr int D2  = J2 ? 3 : 1;
    constexpr int CGO1= H_T1_CG[I2];
    constexpr float PWT = H_T1_PW[I2]*HP_PW[P];

    const int a = v>>2, b = v&3;
    // mid recompute: m[jj] = sum_{ii,kk} xs[a,ii]*xd[b,kk]*CG1
    u64 xsA[D1], xdB[D2];
    #pragma unroll
    for (int ii=0; ii<D1; ii++)
        xsA[ii] = *(const u64*)(sXSp + ((J1 ? (4+a*3+ii) : a)<<6) + pj*2);
    #pragma unroll
    for (int kk=0; kk<D2; kk++)
        xdB[kk] = *(const u64*)(sXDp + ((J2 ? (4+b*3+kk) : b)<<6) + pj*2);
    u64 m[DJ];
    #pragma unroll
    for (int jj=0; jj<DJ; jj++) m[jj]=0ull;
    #pragma unroll
    for (int ii=0; ii<D1; ii++){
        #pragma unroll
        for (int kk=0; kk<D2; kk++){
            u64 pr = mul2(xsA[ii], xdB[kk]);
            #pragma unroll
            for (int jj=0; jj<DJ; jj++)
                fma2(m[jj], pr, dup2(sCG[CGO1 + (ii*D2+kk)*DJ + jj]));
        }
    }
    // z_k = sum_{ii,jj} xs[u,ii]*m[jj]*CG2
    u64 z0=0ull, z1=0ull, z2=0ull;
    #pragma unroll
    for (int ii=0; ii<DI; ii++){
        u64 xu = *(const u64*)(sXSp + ((I1 ? (4+u*3+ii) : u)<<6) + pj*2);
        #pragma unroll
        for (int jj=0; jj<DJ; jj++){
            u64 t = mul2(xu, m[jj]);
            if constexpr (IO==1){
                fma2(z0, t, dup2(sCG[CGO2 + (ii*DJ+jj)*3 + 0]));
                fma2(z1, t, dup2(sCG[CGO2 + (ii*DJ+jj)*3 + 1]));
                fma2(z2, t, dup2(sCG[CGO2 + (ii*DJ+jj)*3 + 2]));
            } else {
                fma2(z0, t, dup2(sCG[CGO2 + ii*DJ+jj]));
            }
        }
    }
    const u64 pw2 = dup2(PWT);
    z0 = mul2(z0, pw2);
    if constexpr (IO==1){ z1 = mul2(z1, pw2); z2 = mul2(z2, pw2); }

    if constexpr (IO==0){
        fma2(outP[w0],   y0, z0);
        fma2(outP[w0+1], y1, z0);
    } else {
        fma2(outP[4+3*w0+0], y0, z0);
        fma2(outP[4+3*w0+1], y0, z1);
        fma2(outP[4+3*w0+2], y0, z2);
        fma2(outP[4+3*(w0+1)+0], y1, z0);
        fma2(outP[4+3*(w0+1)+1], y1, z1);
        fma2(outP[4+3*(w0+1)+2], y1, z2);
    }
}

template<int P>
__device__ __forceinline__ void consume_all(
    int u, int vbase, int w0, int pj,
    const float* __restrict__ sXSp,
    const float* __restrict__ sXDp,
    const float* __restrict__ sCG,
    const float (&C)[8][4],
    u64 (&outP)[16])
{
    #pragma unroll
    for (int nt=0; nt<8; nt++){
        u64 y0 = pk2(C[nt][0], C[nt][2]);
        u64 y1 = pk2(C[nt][1], C[nt][3]);
        consume_one<P>(u, nt*2 + vbase, w0, pj, sXSp, sXDp, sCG, y0, y1, outP);
    }
}

__global__ void zero_kernel(float* out, int n){
    int i = blockIdx.x*blockDim.x + threadIdx.x;
    if (i < n) out[i] = 0.f;
}

// ---------------- main fused conv kernel ----------------
extern "C" __global__ void __launch_bounds__(NTHREADS, 2)
conv_kernel(const float* __restrict__ node_pos,
            const float* __restrict__ edge_type,
            const float* __restrict__ W0g,
            const float* __restrict__ W1g,
            const int*   __restrict__ esrc,
            const int*   __restrict__ edst,
            float* __restrict__ out,
            const __grid_constant__ ConvConsts cc)
{
    extern __shared__ float sm[];
    float* sH   = sm;                 // [64 e][68]   4352 floats (padded, A operand)
    float* sW1  = sH  + 64*68;        // [64 h][136]  8704 (padded, B operand; later scratch)
    float* sXSp = sW1 + 64*136;       // [16 d][32 pair x2] 1024 (edge pairs (e, e+8))
    float* sXDp = sXSp + 1024;        //              1024
    float* sCG  = sXDp + 1024;        //               160
    int*   sSrc = (int*)(sCG + 160);  //                64
    int*   sDst = sSrc + 64;          //                64

    float* sETT = sW1;                // [16 k][64 e] alias, dead after hidden stage
    float* sW0  = sW1 + 1024;         // [16 i][64 h] alias, dead after hidden stage

    const int tid  = threadIdx.x;
    const int wid  = tid >> 5;
    const int lane = tid & 31;
    const int lj   = lane >> 2;   // 0..7
    const int lq   = lane & 3;    // 0..3
    const int mt   = wid >> 1;    // 0..3  (edge tile: rows mt*16..mt*16+15)
    const int nh   = wid & 1;     // 0..1  (column half: nh*64..nh*64+63)
    const int pj   = mt*8 + lj;   // edge-pair index: pair (mt*16+lj, mt*16+lj+8)
    const int e0   = blockIdx.x * TB_E;

    for (int i=tid;i<160;i+=NTHREADS) sCG[i]=cc.cg[i];
    if (tid < 64){ sSrc[tid]=esrc[e0+tid]; sDst[tid]=edst[e0+tid]; }
    __syncthreads();

    // gather node features into packed-pair layout + edge types transposed
    {
        int e=tid>>2, q=tid&3;
        float4 xs = ((const float4*)(node_pos + (size_t)sSrc[e]*16))[q];
        float4 xd = ((const float4*)(node_pos + (size_t)sDst[e]*16))[q];
        float4 t  = ((const float4*)(edge_type + (size_t)(e0+e)*16))[q];
        int j    = ((e>>4)<<3) | (e&7);    // pair index
        int half = (e>>3)&1;               // 0 -> lo slot, 1 -> hi slot
        int base = j*2 + half;
        sXSp[(4*q+0)*64 + base] = xs.x;  sXSp[(4*q+1)*64 + base] = xs.y;
        sXSp[(4*q+2)*64 + base] = xs.z;  sXSp[(4*q+3)*64 + base] = xs.w;
        sXDp[(4*q+0)*64 + base] = xd.x;  sXDp[(4*q+1)*64 + base] = xd.y;
        sXDp[(4*q+2)*64 + base] = xd.z;  sXDp[(4*q+3)*64 + base] = xd.w;
        sETT[(4*q+0)*64 + e] = t.x;   sETT[(4*q+1)*64 + e] = t.y;
        sETT[(4*q+2)*64 + e] = t.z;   sETT[(4*q+3)*64 + e] = t.w;
    }
    for (int i=tid;i<16*64;i+=NTHREADS) sW0[i] = W0g[i]*0.25f;
    __syncthreads();

    // hidden: H[e][h] = silu_c * silu( et[e] . W0[:,h] )   (h across lanes -> coalesced)
    for (int i=tid;i<TB_E*64;i+=NTHREADS){
        int h=i&63, e=i>>6;
        float acc=0.f;
        #pragma unroll
        for (int k=0;k<16;k++) acc += sETT[k*64+e]*sW0[k*64+h];
        sH[e*68+h] = cc.silu_c * acc / (1.f + expf(-acc));
    }

    u64 outP[16];
    #pragma unroll
    for (int k=0;k<16;k++) outP[k]=0ull;

    const int vbase = lq>>1;
    const int w0    = (lq&1)<<1;

    for (int chunk=0; chunk<NCHUNKS; chunk++){
        __syncthreads();
        // load W1 chunk (128 cols) into [64 h][136], scaled 1/8
        for (int i=tid;i<2048;i+=NTHREADS){
            int h=i>>5, c4=i&31;
            float4 w = *((const float4*)(W1g + (size_t)h*WN + chunk*128 + c4*4));
            w.x*=0.125f; w.y*=0.125f; w.z*=0.125f; w.w*=0.125f;
            *((float4*)(sW1 + h*136 + c4*4)) = w;
        }
        __syncthreads();

        // ---- tensor-core GEMM: C[16e x 64n] per warp via tf32 x3 ----
        float C[8][4];
        #pragma unroll
        for (int nt=0;nt<8;nt++){
            C[nt][0]=0.f; C[nt][1]=0.f; C[nt][2]=0.f; C[nt][3]=0.f;
        }
        #pragma unroll
        for (int k8=0;k8<8;k8++){
            const int hb = k8*8;
            float a0f = sH[(mt*16+lj  )*68 + hb+lq  ];
            float a1f = sH[(mt*16+lj+8)*68 + hb+lq  ];
            float a2f = sH[(mt*16+lj  )*68 + hb+lq+4];
            float a3f = sH[(mt*16+lj+8)*68 + hb+lq+4];
            uint32_t a0h,a0l,a1h,a1l,a2h,a2l,a3h,a3l;
            split_tf(a0f,a0h,a0l); split_tf(a1f,a1h,a1l);
            split_tf(a2f,a2h,a2l); split_tf(a3f,a3h,a3l);
            #pragma unroll
            for (int nt=0;nt<8;nt++){
                float b0f = sW1[(hb+lq  )*136 + nh*64 + nt*8 + lj];
                float b1f = sW1[(hb+lq+4)*136 + nh*64 + nt*8 + lj];
                uint32_t b0h,b0l,b1h,b1l;
                split_tf(b0f,b0h,b0l); split_tf(b1f,b1h,b1l);
                mma_tf32(C[nt], a0h,a1h,a2h,a3h, b0h,b1h);
                mma_tf32(C[nt], a0h,a1h,a2h,a3h, b0l,b1l);
                mma_tf32(C[nt], a0l,a1l,a2l,a3l, b0h,b1h);
            }
        }

        // ---- specialized epilogue: p = chunk>>1 uniform; u = (chunk&1)*2 + nh ----
        const int u = ((chunk&1)<<1) | nh;
        switch (chunk >> 1){
            case 0: consume_all<0>(u, vbase, w0, pj, sXSp, sXDp, sCG, C, outP); break;
            case 1: consume_all<1>(u, vbase, w0, pj, sXSp, sXDp, sCG, C, outP); break;
            case 2: consume_all<2>(u, vbase, w0, pj, sXSp, sXDp, sCG, C, outP); break;
            case 3: consume_all<3>(u, vbase, w0, pj, sXSp, sXDp, sCG, C, outP); break;
            case 4: consume_all<4>(u, vbase, w0, pj, sXSp, sXDp, sCG, C, outP); break;
            case 5: consume_all<5>(u, vbase, w0, pj, sXSp, sXDp, sCG, C, outP); break;
            case 6: consume_all<6>(u, vbase, w0, pj, sXSp, sXDp, sCG, C, outP); break;
            case 7: consume_all<7>(u, vbase, w0, pj, sXSp, sXDp, sCG, C, outP); break;
            case 8: consume_all<8>(u, vbase, w0, pj, sXSp, sXDp, sCG, C, outP); break;
            case 9: consume_all<9>(u, vbase, w0, pj, sXSp, sXDp, sCG, C, outP); break;
        }
    }

    // ---- reduce across the 4 lq lanes (same edge pair, different n subsets) ----
    #pragma unroll
    for (int msk=1; msk<4; msk<<=1){
        #pragma unroll
        for (int k=0;k<16;k++){
            u64 o = __shfl_xor_sync(0xffffffffu, outP[k], msk);
            outP[k] = add2(outP[k], o);
        }
    }
    __syncthreads();          // all reads of sH/sW1/sXSp done
    float* sSCR = sW1;        // [2 nh][64 e][16] floats = 2048
    if (lq == 0){
        int r1 = mt*16 + lj;
        #pragma unroll
        for (int k=0;k<16;k++){
            float lo,hi; upk2(outP[k], lo, hi);
            sSCR[(nh*64 + r1  )*16 + k] = lo;
            sSCR[(nh*64 + r1+8)*16 + k] = hi;
        }
    }
    __syncthreads();
    {
        int e  = tid >> 2;
        int dq = tid & 3;
        float4 v0 = *((float4*)(sSCR + e*16 + dq*4));
        float4 v1 = *((float4*)(sSCR + (64+e)*16 + dq*4));
        const float scale = 0.3535533905932738f; // 1/sqrt(NUM_NEIGHBORS=8)
        float* dst = out + (size_t)sDst[e]*16 + dq*4;
        atomicAdd(dst+0, (v0.x+v1.x)*scale);
        atomicAdd(dst+1, (v0.y+v1.y)*scale);
        atomicAdd(dst+2, (v0.z+v1.z)*scale);
        atomicAdd(dst+3, (v0.w+v1.w)*scale);
    }
}

// ---------------- launch ----------------
extern "C" void kernel_launch(void* const* d_in, const int* in_sizes, int n_in,
                              void* d_out, int out_size)
{
    const float* node_pos  = (const float*)d_in[0];
    const float* edge_type = (const float*)d_in[1];
    const float* W0        = (const float*)d_in[2];
    const float* W1        = (const float*)d_in[3];
    const int*   esrc      = (const int*)d_in[4];
    const int*   edst      = (const int*)d_in[5];
    float*       out       = (float*)d_out;

    ConvConsts cc;
    for (int i=0;i<160;i++) cc.cg[i]=0.f;
    real_cg_host(0,0,0, cc.cg+0);
    real_cg_host(0,1,1, cc.cg+1);
    real_cg_host(1,0,1, cc.cg+10);
    real_cg_host(1,1,0, cc.cg+19);
    real_cg_host(1,1,1, cc.cg+28);
    real_cg_host(1,1,2, cc.cg+55);
    real_cg_host(1,2,1, cc.cg+100);

    // SILU_C exactly as the reference computes it (200001-pt grid on [-12,12])
    double dx = 24.0/200000.0, s = 0.0;
    for (int i=0;i<=200000;i++){
        double x   = -12.0 + dx*(double)i;
        double phi = exp(-0.5*x*x)*0.3989422804014327;
        double sl  = x/(1.0+exp(-x));
        s += sl*sl*phi;
    }
    cc.silu_c = (float)(1.0/sqrt(s*dx));

    const int E = in_sizes[4];            // 65536
    const int nblocks = E / TB_E;         // 1024

    // floats: sH 4352 + sW1 8704 + sXSp 1024 + sXDp 1024 + sCG 160, + 128 ints
    size_t smem = (size_t)(4352 + 8704 + 1024 + 1024 + 160)*sizeof(float)
                + 128*sizeof(int);
    cudaFuncSetAttribute(conv_kernel, cudaFuncAttributeMaxDynamicSharedMemorySize, (int)smem);

    zero_kernel<<<(out_size+255)/256,256>>>(out, out_size);
    conv_kernel<<<nblocks, NTHREADS, smem>>>(node_pos, edge_type, W0, W1, esrc, edst, out, cc);
}